// round 14
// baseline (speedup 1.0000x reference)
#include <cuda_runtime.h>
#include <cuda_bf16.h>
#include <math.h>
#include <stdint.h>

// ---------------------------------------------------------------------------
// Per-compilation-pass feature detection (plain compute_103 pass gets fallback)
// ---------------------------------------------------------------------------
#if defined(__CUDA_ARCH__)
# if defined(__CUDA_ARCH_FEAT_SM103_ALL) || defined(__CUDA_ARCH_FEAT_SM100_ALL) || \
     (defined(__CUDA_ARCH_FAMILY_SPECIFIC__) && (__CUDA_ARCH_FAMILY_SPECIFIC__ >= 1000))
#  define HAS_TCGEN05 1
# else
#  define HAS_TCGEN05 0
# endif
#else
# define HAS_TCGEN05 0
#endif

// ---------------------------------------------------------------------------
// Problem constants
// ---------------------------------------------------------------------------
#define B_    8
#define S_    1024
#define D_    1024
#define H_    16
#define DH_   64
#define FF_   4096
#define TOK   (B_ * S_)

// ---------------------------------------------------------------------------
// Scratch. bf16 operand buffers stored TILED: 16KB tiles (128 rows x 64 cols,
// SW128 swizzle pre-applied), tile index (row>>7)*(K>>6) + (col>>6).
// ---------------------------------------------------------------------------
__device__ float g_qkv[(size_t)TOK * 3 * D_];
__device__ float g_x2 [(size_t)TOK * D_];
__device__ __align__(1024) __nv_bfloat16 g_act_hi[(size_t)TOK * D_];
__device__ __align__(1024) __nv_bfloat16 g_act_lo[(size_t)TOK * D_];
__device__ __align__(1024) __nv_bfloat16 g_big_hi[(size_t)TOK * FF_];
__device__ __align__(1024) __nv_bfloat16 g_big_lo[(size_t)TOK * FF_];
__device__ __align__(1024) __nv_bfloat16 g_wqkv_h[(size_t)3 * D_ * D_];
__device__ __align__(1024) __nv_bfloat16 g_wqkv_l[(size_t)3 * D_ * D_];
__device__ __align__(1024) __nv_bfloat16 g_wo_h[(size_t)D_ * D_];
__device__ __align__(1024) __nv_bfloat16 g_wo_l[(size_t)D_ * D_];
__device__ __align__(1024) __nv_bfloat16 g_w1_h[(size_t)FF_ * D_];
__device__ __align__(1024) __nv_bfloat16 g_w1_l[(size_t)FF_ * D_];
__device__ __align__(1024) __nv_bfloat16 g_w2_h[(size_t)D_ * FF_];
__device__ __align__(1024) __nv_bfloat16 g_w2_l[(size_t)D_ * FF_];

// ---------------------------------------------------------------------------
// Tiled-layout addressing (portable)
// ---------------------------------------------------------------------------
__device__ __forceinline__ uint32_t sw128(uint32_t off) { return off ^ ((off >> 3) & 0x70); }

__device__ __forceinline__ size_t tiled_off(int row, int col, int Kk) {
    const int tr = row >> 7, tk = col >> 6;
    const uint32_t inb = ((uint32_t)(row & 127) << 7) | ((uint32_t)(col & 63) << 1);
    return (((size_t)tr * (size_t)(Kk >> 6) + (size_t)tk) << 14) + sw128(inb);
}

// ---------------------------------------------------------------------------
// PTX helpers
// ---------------------------------------------------------------------------
#if HAS_TCGEN05
__device__ __forceinline__ uint32_t smem_u32_of(const void* p) {
    uint32_t a;
    asm("{ .reg .u64 t; cvta.to.shared.u64 t, %1; cvt.u32.u64 %0, t; }" : "=r"(a) : "l"(p));
    return a;
}
#define CLUSTER_SYNC() do { \
    asm volatile("barrier.cluster.arrive.aligned;" ::: "memory"); \
    asm volatile("barrier.cluster.wait.aligned;" ::: "memory"); \
} while (0)

__device__ __forceinline__ void tma_bulk(uint32_t dst, const void* src, uint32_t bytes,
                                         uint32_t mbar) {
    asm volatile(
        "cp.async.bulk.shared::cta.global.mbarrier::complete_tx::bytes [%0], [%1], %2, [%3];"
        :: "r"(dst), "l"(src), "r"(bytes), "r"(mbar) : "memory");
}
__device__ __forceinline__ void l2_prefetch(const void* src, uint32_t bytes) {
    asm volatile("cp.async.bulk.prefetch.L2.global [%0], %1;" :: "l"(src), "r"(bytes));
}
__device__ __forceinline__ void mbar_expect_tx(uint32_t mbar, uint32_t bytes) {
    asm volatile("mbarrier.arrive.expect_tx.shared.b64 _, [%0], %1;"
                 :: "r"(mbar), "r"(bytes) : "memory");
}
// arrive on the mbarrier at the same SMEM offset in cluster CTA `rank`
__device__ __forceinline__ void mbar_arrive_cluster(uint32_t local_addr, uint32_t rank) {
    asm volatile(
        "{\n\t.reg .b32 r;\n\t"
        "mapa.shared::cluster.u32 r, %0, %1;\n\t"
        "mbarrier.arrive.shared::cluster.b64 _, [r];\n\t}"
        :: "r"(local_addr), "r"(rank) : "memory");
}

__device__ __forceinline__ uint64_t smem_desc(uint32_t addr) {
    constexpr uint64_t BASE = (uint64_t(2) << 61)   // SW128
                            | (uint64_t(1) << 46)   // Blackwell
                            | (uint64_t(64) << 32)  // SBO = 64
                            | (uint64_t(1) << 16);  // LBO = 1
    return BASE | ((uint64_t)(addr >> 4) & 0x3FFF);
}
// idesc cg2 kind::f16: d=f32, a=bf16, b=bf16, M_TOTAL=256, N=256
#define GEMM_IDESC2 ((1u<<4) | (1u<<7) | (1u<<10) | ((256u/8)<<17) | ((256u/16)<<24))

__device__ __forceinline__ void mma_f16_ss_cg2(uint32_t d, uint64_t a, uint64_t b,
                                               uint32_t idesc, bool acc) {
    uint32_t e = acc ? 1u : 0u;
    asm volatile(
        "{\n\t.reg .pred p;\n\t"
        "setp.ne.u32 p, %4, 0;\n\t"
        "tcgen05.mma.cta_group::2.kind::f16 [%0], %1, %2, %3, "
        "{%5, %5, %5, %5, %5, %5, %5, %5}, p;\n\t}"
        :: "r"(d), "l"(a), "l"(b), "r"(idesc), "r"(e), "r"(0u) : "memory");
}
__device__ __forceinline__ void mbar_init(uint32_t addr, uint32_t cnt) {
    asm volatile("mbarrier.init.shared.b64 [%0], %1;" :: "r"(addr), "r"(cnt) : "memory");
}
__device__ __forceinline__ void mbar_wait(uint32_t addr, uint32_t parity) {
    asm volatile(
        "{\n\t.reg .pred P;\n\t"
        "W%=:\n\t"
        "mbarrier.try_wait.parity.acquire.cta.shared::cta.b64 P, [%0], %1, 0x989680;\n\t"
        "@!P bra W%=;\n\t}"
        :: "r"(addr), "r"(parity) : "memory");
}

#define TC_ALLOC_CG2(sm, n)  asm volatile("tcgen05.alloc.cta_group::2.sync.aligned.shared::cta.b32 [%0], %1;" :: "r"(sm), "r"(n) : "memory")
#define TC_RELINQ_CG2()      asm volatile("tcgen05.relinquish_alloc_permit.cta_group::2.sync.aligned;")
#define TC_DEALLOC_CG2(t, n) asm volatile("tcgen05.dealloc.cta_group::2.sync.aligned.b32 %0, %1;" :: "r"(t), "r"(n))
#define TC_COMMIT_MC_CG2(mb, mask) \
    asm volatile("tcgen05.commit.cta_group::2.mbarrier::arrive::one.shared::cluster.multicast::cluster.b64 [%0], %1;" \
                 :: "r"(mb), "h"((uint16_t)(mask)) : "memory")
#define TC_FENCE_AFTER()  asm volatile("tcgen05.fence::after_thread_sync;" ::: "memory")
#define TC_FENCE_BEFORE() asm volatile("tcgen05.fence::before_thread_sync;" ::: "memory")
#define TC_WAIT_LD()      asm volatile("tcgen05.wait::ld.sync.aligned;" ::: "memory")

#define TC_LD_X32(r, t) \
    asm volatile( \
        "tcgen05.ld.sync.aligned.32x32b.x32.b32 " \
        "{%0, %1, %2, %3, %4, %5, %6, %7, " \
        " %8, %9, %10, %11, %12, %13, %14, %15, " \
        " %16, %17, %18, %19, %20, %21, %22, %23, " \
        " %24, %25, %26, %27, %28, %29, %30, %31}, [%32];" \
        : "=r"((r)[0]),  "=r"((r)[1]),  "=r"((r)[2]),  "=r"((r)[3]), \
          "=r"((r)[4]),  "=r"((r)[5]),  "=r"((r)[6]),  "=r"((r)[7]), \
          "=r"((r)[8]),  "=r"((r)[9]),  "=r"((r)[10]), "=r"((r)[11]), \
          "=r"((r)[12]), "=r"((r)[13]), "=r"((r)[14]), "=r"((r)[15]), \
          "=r"((r)[16]), "=r"((r)[17]), "=r"((r)[18]), "=r"((r)[19]), \
          "=r"((r)[20]), "=r"((r)[21]), "=r"((r)[22]), "=r"((r)[23]), \
          "=r"((r)[24]), "=r"((r)[25]), "=r"((r)[26]), "=r"((r)[27]), \
          "=r"((r)[28]), "=r"((r)[29]), "=r"((r)[30]), "=r"((r)[31]) \
        : "r"(t))

// ---- packed f32x2 (Blackwell) ----
__device__ __forceinline__ uint64_t pack2f(float lo, float hi) {
    uint64_t r;
    asm("mov.b64 %0, {%1, %2};" : "=l"(r) : "f"(lo), "f"(hi));
    return r;
}
__device__ __forceinline__ void unpack2f(uint64_t v, float& lo, float& hi) {
    asm("mov.b64 {%0, %1}, %2;" : "=f"(lo), "=f"(hi) : "l"(v));
}
__device__ __forceinline__ void ffma2(uint64_t& d, uint64_t a, uint64_t b) {
    asm("fma.rn.f32x2 %0, %1, %2, %3;" : "=l"(d) : "l"(a), "l"(b), "l"(d));
}
__device__ __forceinline__ void fadd2(uint64_t& d, uint64_t a) {
    asm("add.rn.f32x2 %0, %1, %2;" : "=l"(d) : "l"(d), "l"(a));
}
__device__ __forceinline__ void fmul2(uint64_t& d, uint64_t a) {
    asm("mul.rn.f32x2 %0, %1, %2;" : "=l"(d) : "l"(d), "l"(a));
}
#endif  // HAS_TCGEN05

// ---------------------------------------------------------------------------
// fp32 -> bf16 (hi, lo) split store into TILED buffers
// ---------------------------------------------------------------------------
__device__ __forceinline__ void split_store4_tiled(__nv_bfloat16* __restrict__ hi,
                                                   __nv_bfloat16* __restrict__ lo,
                                                   int row, int col, int Kk, float4 v) {
    const size_t off = tiled_off(row, col, Kk);
    __nv_bfloat16 h0 = __float2bfloat16(v.x);
    __nv_bfloat16 h1 = __float2bfloat16(v.y);
    __nv_bfloat16 h2 = __float2bfloat16(v.z);
    __nv_bfloat16 h3 = __float2bfloat16(v.w);
    __nv_bfloat16 l0 = __float2bfloat16(v.x - __bfloat162float(h0));
    __nv_bfloat16 l1 = __float2bfloat16(v.y - __bfloat162float(h1));
    __nv_bfloat16 l2 = __float2bfloat16(v.z - __bfloat162float(h2));
    __nv_bfloat16 l3 = __float2bfloat16(v.w - __bfloat162float(h3));
    __nv_bfloat162 ha; ha.x = h0; ha.y = h1;
    __nv_bfloat162 hb; hb.x = h2; hb.y = h3;
    __nv_bfloat162 la; la.x = l0; la.y = l1;
    __nv_bfloat162 lb; lb.x = l2; lb.y = l3;
    *(__nv_bfloat162*)((char*)hi + off)     = ha;
    *(__nv_bfloat162*)((char*)hi + off + 4) = hb;
    *(__nv_bfloat162*)((char*)lo + off)     = la;
    *(__nv_bfloat162*)((char*)lo + off + 4) = lb;
}

__global__ __launch_bounds__(256)
void split_kernel(const float* __restrict__ x,
                  __nv_bfloat16* __restrict__ hi,
                  __nv_bfloat16* __restrict__ lo, int n4, int K)
{
    int i = blockIdx.x * 256 + threadIdx.x;
    if (i < n4) {
        float4 v = ((const float4*)x)[i];
        const int e = i << 2;
        split_store4_tiled(hi, lo, e / K, e % K, K, v);
    }
}

// ---------------------------------------------------------------------------
// LayerNorm fused with tiled bf16 split output
// ---------------------------------------------------------------------------
__global__ __launch_bounds__(256)
void ln_split_kernel(const float* __restrict__ x,
                     const float* __restrict__ gw,
                     const float* __restrict__ bw,
                     __nv_bfloat16* __restrict__ out_hi,
                     __nv_bfloat16* __restrict__ out_lo)
{
    __shared__ float red[16];
    const int row = blockIdx.x;
    const int tid = threadIdx.x;

    const float4 v = ((const float4*)(x + (size_t)row * D_))[tid];
    float s  = v.x + v.y + v.z + v.w;
    float ss = v.x*v.x + v.y*v.y + v.z*v.z + v.w*v.w;

    #pragma unroll
    for (int o = 16; o; o >>= 1) {
        s  += __shfl_xor_sync(0xffffffffu, s,  o);
        ss += __shfl_xor_sync(0xffffffffu, ss, o);
    }
    const int wid = tid >> 5, lid = tid & 31;
    if (lid == 0) { red[wid] = s; red[8 + wid] = ss; }
    __syncthreads();

    float sum = 0.f, sq = 0.f;
    #pragma unroll
    for (int i = 0; i < 8; i++) { sum += red[i]; sq += red[8 + i]; }

    const float mu  = sum * (1.0f / D_);
    const float var = sq  * (1.0f / D_) - mu * mu;
    const float rs  = rsqrtf(var + 1e-5f);

    const float4 g4 = ((const float4*)gw)[tid];
    const float4 b4 = ((const float4*)bw)[tid];
    float4 o;
    o.x = (v.x - mu) * rs * g4.x + b4.x;
    o.y = (v.y - mu) * rs * g4.y + b4.y;
    o.z = (v.z - mu) * rs * g4.z + b4.z;
    o.w = (v.w - mu) * rs * g4.w + b4.w;
    split_store4_tiled(out_hi, out_lo, row, tid * 4, D_, o);
}

// ---------------------------------------------------------------------------
// GEMM (TN), cg2 2-CTA tcgen05: pair tile M=256 x N=256, BK=64, 3 stages of
// 64KB per CTA, cluster (2,1,1). Producer also issues L2 prefetch for stage
// t+3 (latency hiding beyond the SMEM ring).
// ---------------------------------------------------------------------------
enum { EPI_BIAS = 0, EPI_BIAS_RES = 1, EPI_GELU_SPLIT = 2 };

__device__ __forceinline__ float gelu_tanh(float x)
{
    const float u = 0.7978845608028654f * (x + 0.044715f * x * x * x);
    return 0.5f * x * (1.0f + tanhf(u));
}

#define STAGE_BYTES 65536
#define SMEM_GEMM   (1024 + 3 * STAGE_BYTES)

template <int EPI>
__global__ __launch_bounds__(256, 1) __cluster_dims__(2, 1, 1)
void gemm_tc(const __nv_bfloat16* __restrict__ Ah, const __nv_bfloat16* __restrict__ Al,
             const __nv_bfloat16* __restrict__ Bh, const __nv_bfloat16* __restrict__ Bl,
             const float* __restrict__ bias, const float* __restrict__ resid,
             float* __restrict__ Cf,
             __nv_bfloat16* __restrict__ Chi, __nv_bfloat16* __restrict__ Clo,
             int N, int K)
{
#if HAS_TCGEN05
    extern __shared__ char smem[];
    const uint32_t sm = smem_u32_of(smem);
    const int tid = threadIdx.x;
    const int wid = tid >> 5;
    const int lid = tid & 31;
    const int my  = blockIdx.x;            // this CTA's 128-row A block
    const int m0  = my << 7;
    const int nb0 = blockIdx.y * 2;        // first of two 128-row B blocks
    const int n0  = blockIdx.y << 8;
    const int rank = blockIdx.x & 1;       // cluster_ctarank for (2,1,1)
    const int KT  = K >> 6;
    const int T   = KT;

    if (tid == 0) {
        mbar_init(sm + 8, 1);  mbar_init(sm + 16, 1);  mbar_init(sm + 24, 1);
        const uint32_t fcnt = (rank == 0) ? 2u : 1u;
        mbar_init(sm + 32, fcnt); mbar_init(sm + 40, fcnt); mbar_init(sm + 48, fcnt);
        mbar_init(sm + 56, 1);
    }
    if (wid == 0) {
        TC_ALLOC_CG2(sm, 256);
        TC_RELINQ_CG2();
    }
    __syncthreads();

    uint32_t tmem;
    asm volatile("ld.shared.b32 %0, [%1];" : "=r"(tmem) : "r"(sm));

    CLUSTER_SYNC();

    if (tid == 32) {
        // ------------- TMA producer: own A half + own B half + L2 prefetch --
        const char* pAh = (const char*)Ah;
        const char* pAl = (const char*)Al;
        const char* pBh = (const char*)Bh;
        const char* pBl = (const char*)Bl;
        // prefetch the first 3 stages' successors early
        #pragma unroll
        for (int pt = 0; pt < 3; pt++) {
            if (pt < T) {
                const size_t aoff = ((size_t)(my * KT + pt)) << 14;
                const size_t boff = ((size_t)((nb0 + rank) * KT + pt)) << 14;
                l2_prefetch(pAh + aoff, 16384);
                l2_prefetch(pAl + aoff, 16384);
                l2_prefetch(pBh + boff, 16384);
                l2_prefetch(pBl + boff, 16384);
            }
        }
        for (int t = 0; t < T; ++t) {
            const int s = t % 3;
            if (t >= 3) mbar_wait(sm + 8 + s * 8, ((t / 3) - 1) & 1);
            const uint32_t sb = sm + 1024 + s * STAGE_BYTES;
            const uint32_t fb = sm + 32 + s * 8;
            mbar_expect_tx(fb, STAGE_BYTES);
            const size_t aoff = ((size_t)(my * KT + t)) << 14;
            const size_t boff = ((size_t)((nb0 + rank) * KT + t)) << 14;
            tma_bulk(sb,         pAh + aoff, 16384, fb);
            tma_bulk(sb + 16384, pAl + aoff, 16384, fb);
            tma_bulk(sb + 32768, pBh + boff, 16384, fb);
            tma_bulk(sb + 49152, pBl + boff, 16384, fb);
            // L2 prefetch stage t+3 (3 stages beyond SMEM ring lookahead)
            if (t + 3 < T) {
                const size_t aoff3 = ((size_t)(my * KT + t + 3)) << 14;
                const size_t boff3 = ((size_t)((nb0 + rank) * KT + t + 3)) << 14;
                l2_prefetch(pAh + aoff3, 16384);
                l2_prefetch(pAl + aoff3, 16384);
                l2_prefetch(pBh + boff3, 16384);
                l2_prefetch(pBl + boff3, 16384);
            }
        }
    } else if (tid == 0) {
        if (rank == 0) {
            // ------------------- MMA issuer (leader) ------------------------
            uint64_t dAh[3], dAl[3], dBh[3], dBl[3];
            #pragma unroll
            for (int s = 0; s < 3; s++) {
                const uint32_t sb = sm + 1024 + s * STAGE_BYTES;
                dAh[s] = smem_desc(sb);
                dAl[s] = smem_desc(sb + 16384);
                dBh[s] = smem_desc(sb + 32768);
                dBl[s] = smem_desc(sb + 49152);
            }
            for (int t = 0; t < T; ++t) {
                const int s = t % 3;
                mbar_wait(sm + 32 + s * 8, (t / 3) & 1);
                #pragma unroll
                for (int ks = 0; ks < 4; ks++) {
                    mma_f16_ss_cg2(tmem, dAh[s] + ks*2, dBh[s] + ks*2, GEMM_IDESC2,
                                   !(t == 0 && ks == 0));
                    mma_f16_ss_cg2(tmem, dAh[s] + ks*2, dBl[s] + ks*2, GEMM_IDESC2, true);
                    mma_f16_ss_cg2(tmem, dAl[s] + ks*2, dBh[s] + ks*2, GEMM_IDESC2, true);
                }
                TC_COMMIT_MC_CG2(sm + 8 + s * 8, 0x3);   // done[s] -> both CTAs
            }
            TC_COMMIT_MC_CG2(sm + 56, 0x3);              // fin -> both CTAs
        } else {
            // --------------- follower: forward tx-complete to leader --------
            for (int t = 0; t < T; ++t) {
                const int s = t % 3;
                mbar_wait(sm + 32 + s * 8, (t / 3) & 1);   // local full[s]
                mbar_arrive_cluster(sm + 32 + s * 8, 0);   // leader full[s]
            }
        }
    }

    // ALL threads (both CTAs) wait the single-phase fin barrier
    mbar_wait(sm + 56, 0);
    TC_FENCE_AFTER();

    // epilogue: this CTA's 128 TMEM lanes hold D rows m0..m0+127
    const int m = m0 + (wid & 3) * 32 + lid;
    const int cb0 = (wid >> 2) * 4;
    #pragma unroll
    for (int cc = 0; cc < 4; cc++) {
        const int cb = cb0 + cc;
        uint32_t dr[32];
        TC_LD_X32(dr, tmem + cb * 32);
        TC_WAIT_LD();
        const int nb = n0 + cb * 32;
        if (EPI == EPI_GELU_SPLIT) {
            #pragma unroll
            for (int j = 0; j < 32; j += 4) {
                float4 v;
                v.x = gelu_tanh(__uint_as_float(dr[j])     + bias[nb + j]);
                v.y = gelu_tanh(__uint_as_float(dr[j + 1]) + bias[nb + j + 1]);
                v.z = gelu_tanh(__uint_as_float(dr[j + 2]) + bias[nb + j + 2]);
                v.w = gelu_tanh(__uint_as_float(dr[j + 3]) + bias[nb + j + 3]);
                split_store4_tiled(Chi, Clo, m, nb + j, N, v);
            }
        } else {
            #pragma unroll
            for (int j = 0; j < 32; j += 4) {
                float4 v;
                v.x = __uint_as_float(dr[j])     + bias[nb + j];
                v.y = __uint_as_float(dr[j + 1]) + bias[nb + j + 1];
                v.z = __uint_as_float(dr[j + 2]) + bias[nb + j + 2];
                v.w = __uint_as_float(dr[j + 3]) + bias[nb + j + 3];
                if (EPI == EPI_BIAS_RES) {
                    const float4 rr = *(const float4*)(resid + (size_t)m * N + nb + j);
                    v.x += rr.x; v.y += rr.y; v.z += rr.z; v.w += rr.w;
                }
                *(float4*)(Cf + (size_t)m * N + nb + j) = v;
            }
        }
    }
    TC_FENCE_BEFORE();
    __syncthreads();
    if (wid == 0) TC_DEALLOC_CG2(tmem, 256);
    CLUSTER_SYNC();

#else  // ------------------- portable SIMT fallback (256 threads) ----------
    extern __shared__ char smem[];
    float* As = (float*)smem;
    float* Bs = (float*)(smem + 16 * 128 * 4);
    const int tid = threadIdx.x;
    const int m0 = blockIdx.x * 128;
    const int ty = tid >> 4;
    const int tx = tid & 15;

    for (int nh = 0; nh < 2; nh++) {
        const int n0 = blockIdx.y * 256 + nh * 128;
        float acc[8][8];
        #pragma unroll
        for (int i = 0; i < 8; i++)
            #pragma unroll
            for (int j = 0; j < 8; j++) acc[i][j] = 0.f;

        for (int k0 = 0; k0 < K; k0 += 16) {
            __syncthreads();
            #pragma unroll 4
            for (int i = tid; i < 2048; i += 256) {
                const int r = i >> 4, c = i & 15;
                const size_t oa = tiled_off(m0 + r, k0 + c, K);
                As[c * 128 + r] =
                    __bfloat162float(*(const __nv_bfloat16*)((const char*)Ah + oa)) +
                    __bfloat162float(*(const __nv_bfloat16*)((const char*)Al + oa));
                const size_t ob = tiled_off(n0 + r, k0 + c, K);
                Bs[c * 128 + r] =
                    __bfloat162float(*(const __nv_bfloat16*)((const char*)Bh + ob)) +
                    __bfloat162float(*(const __nv_bfloat16*)((const char*)Bl + ob));
            }
            __syncthreads();
            #pragma unroll
            for (int kk = 0; kk < 16; kk++) {
                float a[8], b[8];
                #pragma unroll
                for (int i = 0; i < 8; i++) a[i] = As[kk * 128 + ty * 8 + i];
                #pragma unroll
                for (int j = 0; j < 8; j++) b[j] = Bs[kk * 128 + tx * 8 + j];
                #pragma unroll
                for (int i = 0; i < 8; i++)
                    #pragma unroll
                    for (int j = 0; j < 8; j++)
                        acc[i][j] = fmaf(a[i], b[j], acc[i][j]);
            }
        }

        #pragma unroll
        for (int i = 0; i < 8; i++) {
            const int m = m0 + ty * 8 + i;
            #pragma unroll
            for (int j = 0; j < 8; j++) {
                const int n = n0 + tx * 8 + j;
                float v = acc[i][j] + bias[n];
                if (EPI == EPI_GELU_SPLIT) {
                    v = gelu_tanh(v);
                    __nv_bfloat16 hv = __float2bfloat16(v);
                    const size_t oc = tiled_off(m, n, N);
                    *(__nv_bfloat16*)((char*)Chi + oc) = hv;
                    *(__nv_bfloat16*)((char*)Clo + oc) =
                        __float2bfloat16(v - __bfloat162float(hv));
                } else {
                    if (EPI == EPI_BIAS_RES) v += resid[(size_t)m * N + n];
                    Cf[(size_t)m * N + n] = v;
                }
            }
        }
        __syncthreads();
    }
#endif
}

// ---------------------------------------------------------------------------
// Causal flash attention: 128 queries/block, 1 thread per query, 64-key K/V
// tiles in smem, packed f32x2 FMA inner loops. Output: tiled bf16 split.
// ---------------------------------------------------------------------------
__global__ __launch_bounds__(128)
void attn_kernel(const float* __restrict__ qkv,
                 __nv_bfloat16* __restrict__ out_hi,
                 __nv_bfloat16* __restrict__ out_lo)
{
    __shared__ float k_s[64][68];
    __shared__ float v_s[64][64];

    const int qt = blockIdx.x;
    const int bh = blockIdx.y;
    const int b  = bh >> 4;
    const int h  = bh & 15;
    const int t  = threadIdx.x;
    const int g  = qt * 128 + t;

    const size_t seq_base = (size_t)b * S_ * (3 * D_);
    const size_t head_off = (size_t)h * DH_;
    const int numkt = 2 * qt + 2;
    const int orow = b * S_ + g;

#if HAS_TCGEN05
    uint64_t qp[32];
    {
        const ulonglong2* q128 = (const ulonglong2*)(qkv + seq_base + head_off +
                                                     (size_t)g * (3 * D_));
        #pragma unroll
        for (int i = 0; i < 16; i++) {
            const ulonglong2 u = q128[i];
            qp[2*i] = u.x; qp[2*i+1] = u.y;
        }
    }
    uint64_t op[32];
    #pragma unroll
    for (int i = 0; i < 32; i++) op[i] = 0ull;
    float m = -1e30f, l = 0.f;

    for (int kt = 0; kt < numkt; kt++) {
        const float* kp = qkv + seq_base + D_     + head_off + (size_t)(kt * 64) * (3 * D_);
        const float* vp = qkv + seq_base + 2 * D_ + head_off + (size_t)(kt * 64) * (3 * D_);
        #pragma unroll 4
        for (int i = t; i < 64 * 16; i += 128) {
            const int r = i >> 4;
            const int c = (i & 15) << 2;
            *(float4*)&k_s[r][c] = *(const float4*)(kp + (size_t)r * (3 * D_) + c);
            *(float4*)&v_s[r][c] = *(const float4*)(vp + (size_t)r * (3 * D_) + c);
        }
        __syncthreads();

        const bool edge = (kt >= 2 * qt);
        #pragma unroll
        for (int half = 0; half < 2; half++) {
            const int kbase = half * 32;
            float s[32];
            float mt = -1e30f;
            #pragma unroll 2
            for (int kc = 0; kc < 32; kc++) {
                const ulonglong2* krow = (const ulonglong2*)k_s[kbase + kc];
                uint64_t a0 = 0ull, a1 = 0ull, a2 = 0ull, a3 = 0ull;
                #pragma unroll
                for (int i = 0; i < 8; i++) {
                    const ulonglong2 u0 = krow[2*i];
                    const ulonglong2 u1 = krow[2*i+1];
                    ffma2(a0, qp[4*i],   u0.x);
                    ffma2(a1, qp[4*i+1], u0.y);
                    ffma2(a2, qp[4*i+2], u1.x);
                    ffma2(a3, qp[4*i+3], u1.y);
                }
                fadd2(a0, a2); fadd2(a1, a3); fadd2(a0, a1);
                float lo, hi; unpack2f(a0, lo, hi);
                float sc = (lo + hi) * 0.125f;
                if (edge && (kt * 64 + kbase + kc) > g) sc = -1e30f;
                s[kc] = sc;
                mt = fmaxf(mt, sc);
            }
            const float m_new = fmaxf(m, mt);
            const float corr  = __expf(m - m_new);
            l *= corr;
            const uint64_t corr2 = pack2f(corr, corr);
            #pragma unroll
            for (int i = 0; i < 32; i++) fmul2(op[i], corr2);
            #pragma unroll 2
            for (int kc = 0; kc < 32; kc++) {
                const float p = __expf(s[kc] - m_new);
                l += p;
                const uint64_t p2 = pack2f(p, p);
                const ulonglong2* vrow = (const ulonglong2*)v_s[kbase + kc];
                #pragma unroll
                for (int i = 0; i < 16; i++) {
                    const ulonglong2 u = vrow[i];
                    ffma2(op[2*i],   p2, u.x);
                    ffma2(op[2*i+1], p2, u.y);
                }
            }
            m = m_new;
        }
        __syncthreads();
    }

    const float inv_l = 1.0f / l;
    #pragma unroll
    for (int i = 0; i < 16; i++) {
        float4 v;
        unpack2f(op[2*i],   v.x, v.y);
        unpack2f(op[2*i+1], v.z, v.w);
        v.x *= inv_l; v.y *= inv_l; v.z *= inv_l; v.w *= inv_l;
        split_store4_tiled(out_hi, out_lo, orow, (int)head_off + i * 4, D_, v);
    }

#else
    float q[64];
    {
        const float* qpt = qkv + seq_base + head_off + (size_t)g * (3 * D_);
        #pragma unroll
        for (int d = 0; d < 64; d += 4) {
            const float4 u = *(const float4*)(qpt + d);
            q[d] = u.x; q[d+1] = u.y; q[d+2] = u.z; q[d+3] = u.w;
        }
    }
    float o[64];
    #pragma unroll
    for (int d = 0; d < 64; d++) o[d] = 0.f;
    float m = -1e30f, l = 0.f;

    for (int kt = 0; kt < numkt; kt++) {
        const float* kp = qkv + seq_base + D_     + head_off + (size_t)(kt * 64) * (3 * D_);
        const float* vp = qkv + seq_base + 2 * D_ + head_off + (size_t)(kt * 64) * (3 * D_);
        #pragma unroll 4
        for (int i = t; i < 64 * 16; i += 128) {
            const int r = i >> 4;
            const int c = (i & 15) << 2;
            *(float4*)&k_s[r][c] = *(const float4*)(kp + (size_t)r * (3 * D_) + c);
            *(float4*)&v_s[r][c] = *(const float4*)(vp + (size_t)r * (3 * D_) + c);
        }
        __syncthreads();

        const bool edge = (kt >= 2 * qt);
        #pragma unroll
        for (int half = 0; half < 2; half++) {
            const int kbase = half * 32;
            float s[32];
            float mt = -1e30f;
            #pragma unroll 2
            for (int kc = 0; kc < 32; kc++) {
                const float4* krow = (const float4*)k_s[kbase + kc];
                float d0 = 0.f, d1 = 0.f, d2 = 0.f, d3 = 0.f;
                #pragma unroll
                for (int d4 = 0; d4 < 16; d4++) {
                    const float4 kv = krow[d4];
                    d0 = fmaf(q[4*d4+0], kv.x, d0);
                    d1 = fmaf(q[4*d4+1], kv.y, d1);
                    d2 = fmaf(q[4*d4+2], kv.z, d2);
                    d3 = fmaf(q[4*d4+3], kv.w, d3);
                }
                float sc = (d0 + d1 + d2 + d3) * 0.125f;
                if (edge && (kt * 64 + kbase + kc) > g) sc = -1e30f;
                s[kc] = sc;
                mt = fmaxf(mt, sc);
            }
            const float m_new = fmaxf(m, mt);
            const float corr  = __expf(m - m_new);
            l *= corr;
            #pragma unroll
            for (int d = 0; d < 64; d++) o[d] *= corr;
            #pragma unroll 2
            for (int kc = 0; kc < 32; kc++) {
                const float p = __expf(s[kc] - m_new);
                l += p;
                const float4* vrow = (const float4*)v_s[kbase + kc];
                #pragma unroll
                for (int d4 = 0; d4 < 16; d4++) {
                    const float4 vv = vrow[d4];
                    o[4*d4+0] = fmaf(p, vv.x, o[4*d4+0]);
                    o[4*d4+1] = fmaf(p, vv.y, o[4*d4+1]);
                    o[4*d4+2] = fmaf(p, vv.z, o[4*d4+2]);
                    o[4*d4+3] = fmaf(p, vv.w, o[4*d4+3]);
                }
            }
            m = m_new;
        }
        __syncthreads();
    }

    const float inv_l = 1.0f / l;
    #pragma unroll
    for (int d4 = 0; d4 < 16; d4++) {
        float4 v;
        v.x = o[4*d4+0] * inv_l;
        v.y = o[4*d4+1] * inv_l;
        v.z = o[4*d4+2] * inv_l;
        v.w = o[4*d4+3] * inv_l;
        split_store4_tiled(out_hi, out_lo, orow, (int)head_off + d4 * 4, D_, v);
    }
#endif
}

// ---------------------------------------------------------------------------
// Launch: fork-join streams — weight splits overlap LN1/QKV/attention.
// ---------------------------------------------------------------------------
extern "C" void kernel_launch(void* const* d_in, const int* in_sizes, int n_in,
                              void* d_out, int out_size)
{
    const float* x     = (const float*)d_in[0];
    const float* ln1_g = (const float*)d_in[1];
    const float* ln1_b = (const float*)d_in[2];
    const float* w_qkv = (const float*)d_in[3];
    const float* b_qkv = (const float*)d_in[4];
    const float* w_o   = (const float*)d_in[5];
    const float* b_o   = (const float*)d_in[6];
    const float* ln2_g = (const float*)d_in[7];
    const float* ln2_b = (const float*)d_in[8];
    const float* w1    = (const float*)d_in[9];
    const float* b1    = (const float*)d_in[10];
    const float* w2    = (const float*)d_in[11];
    const float* b2    = (const float*)d_in[12];
    float* out = (float*)d_out;

    static bool inited = false;
    static float *p_qkv, *p_x2;
    static __nv_bfloat16 *p_act_h, *p_act_l, *p_big_h, *p_big_l;
    static __nv_bfloat16 *p_wqkv_h, *p_wqkv_l, *p_wo_h, *p_wo_l;
    static __nv_bfloat16 *p_w1_h, *p_w1_l, *p_w2_h, *p_w2_l;
    static cudaStream_t s2;
    static cudaEvent_t ev0, evq, ev1;
    if (!inited) {
        void* p;
        cudaGetSymbolAddress(&p, g_qkv);    p_qkv    = (float*)p;
        cudaGetSymbolAddress(&p, g_x2);     p_x2     = (float*)p;
        cudaGetSymbolAddress(&p, g_act_hi); p_act_h  = (__nv_bfloat16*)p;
        cudaGetSymbolAddress(&p, g_act_lo); p_act_l  = (__nv_bfloat16*)p;
        cudaGetSymbolAddress(&p, g_big_hi); p_big_h  = (__nv_bfloat16*)p;
        cudaGetSymbolAddress(&p, g_big_lo); p_big_l  = (__nv_bfloat16*)p;
        cudaGetSymbolAddress(&p, g_wqkv_h); p_wqkv_h = (__nv_bfloat16*)p;
        cudaGetSymbolAddress(&p, g_wqkv_l); p_wqkv_l = (__nv_bfloat16*)p;
        cudaGetSymbolAddress(&p, g_wo_h);   p_wo_h   = (__nv_bfloat16*)p;
        cudaGetSymbolAddress(&p, g_wo_l);   p_wo_l   = (__nv_bfloat16*)p;
        cudaGetSymbolAddress(&p, g_w1_h);   p_w1_h   = (__nv_bfloat16*)p;
        cudaGetSymbolAddress(&p, g_w1_l);   p_w1_l   = (__nv_bfloat16*)p;
        cudaGetSymbolAddress(&p, g_w2_h);   p_w2_h   = (__nv_bfloat16*)p;
        cudaGetSymbolAddress(&p, g_w2_l);   p_w2_l   = (__nv_bfloat16*)p;
        cudaFuncSetAttribute(gemm_tc<EPI_BIAS>,       cudaFuncAttributeMaxDynamicSharedMemorySize, SMEM_GEMM);
        cudaFuncSetAttribute(gemm_tc<EPI_BIAS_RES>,   cudaFuncAttributeMaxDynamicSharedMemorySize, SMEM_GEMM);
        cudaFuncSetAttribute(gemm_tc<EPI_GELU_SPLIT>, cudaFuncAttributeMaxDynamicSharedMemorySize, SMEM_GEMM);
        cudaStreamCreateWithFlags(&s2, cudaStreamNonBlocking);
        cudaEventCreateWithFlags(&ev0, cudaEventDisableTiming);
        cudaEventCreateWithFlags(&evq, cudaEventDisableTiming);
        cudaEventCreateWithFlags(&ev1, cudaEventDisableTiming);
        inited = true;
    }

    // fork: s2 handles all weight splits
    cudaEventRecord(ev0, 0);
    cudaStreamWaitEvent(s2, ev0, 0);
    split_kernel<<<(3*D_*D_/4 + 255)/256, 256, 0, s2>>>(w_qkv, p_wqkv_h, p_wqkv_l, 3*D_*D_/4, D_);
    cudaEventRecord(evq, s2);   // w_qkv split done (needed by QKV GEMM)
    split_kernel<<<(D_*D_/4   + 255)/256, 256, 0, s2>>>(w_o,   p_wo_h,   p_wo_l,   D_*D_/4,   D_);
    split_kernel<<<(FF_*D_/4  + 255)/256, 256, 0, s2>>>(w1,    p_w1_h,   p_w1_l,   FF_*D_/4,  D_);
    split_kernel<<<(D_*FF_/4  + 255)/256, 256, 0, s2>>>(w2,    p_w2_h,   p_w2_l,   D_*FF_/4,  FF_);
    cudaEventRecord(ev1, s2);   // all splits done (needed by o-proj/FFN)

    // main stream
    // 1. LN1 + split (tiled) — overlaps w_qkv split
    ln_split_kernel<<<TOK, 256>>>(x, ln1_g, ln1_b, p_act_h, p_act_l);

    // 2. QKV projection (needs w_qkv split)
    cudaStreamWaitEvent(0, evq, 0);
    gemm_tc<EPI_BIAS><<<dim3(TOK/128, 3*D_/256), 256, SMEM_GEMM>>>(
        p_act_h, p_act_l, p_wqkv_h, p_wqkv_l, b_qkv, nullptr,
        p_qkv, nullptr, nullptr, 3*D_, D_);

    // 3. causal attention — overlaps remaining splits
    attn_kernel<<<dim3(S_/128, B_*H_), 128>>>(p_qkv, p_act_h, p_act_l);

    // join before o-proj (needs w_o)
    cudaStreamWaitEvent(0, ev1, 0);

    // 4. output projection + residual
    gemm_tc<EPI_BIAS_RES><<<dim3(TOK/128, D_/256), 256, SMEM_GEMM>>>(
        p_act_h, p_act_l, p_wo_h, p_wo_l, b_o, x,
        p_x2, nullptr, nullptr, D_, D_);

    // 5. LN2 + split (tiled)
    ln_split_kernel<<<TOK, 256>>>(p_x2, ln2_g, ln2_b, p_act_h, p_act_l);

    // 6. FFN up + GELU + split (tiled)
    gemm_tc<EPI_GELU_SPLIT><<<dim3(TOK/128, FF_/256), 256, SMEM_GEMM>>>(
        p_act_h, p_act_l, p_w1_h, p_w1_l, b1, nullptr,
        nullptr, p_big_h, p_big_l, FF_, D_);

    // 7. FFN down + residual -> out
    gemm_tc<EPI_BIAS_RES><<<dim3(TOK/128, D_/256), 256, SMEM_GEMM>>>(
        p_big_h, p_big_l, p_w2_h, p_w2_l, b2, p_x2,
        out, nullptr, nullptr, D_, FF_);
}

// round 16
// speedup vs baseline: 1.0329x; 1.0329x over previous
#include <cuda_runtime.h>
#include <cuda_bf16.h>
#include <math.h>
#include <stdint.h>

// ---------------------------------------------------------------------------
// Per-compilation-pass feature detection (plain compute_103 pass gets fallback)
// ---------------------------------------------------------------------------
#if defined(__CUDA_ARCH__)
# if defined(__CUDA_ARCH_FEAT_SM103_ALL) || defined(__CUDA_ARCH_FEAT_SM100_ALL) || \
     (defined(__CUDA_ARCH_FAMILY_SPECIFIC__) && (__CUDA_ARCH_FAMILY_SPECIFIC__ >= 1000))
#  define HAS_TCGEN05 1
# else
#  define HAS_TCGEN05 0
# endif
#else
# define HAS_TCGEN05 0
#endif

// ---------------------------------------------------------------------------
// Problem constants
// ---------------------------------------------------------------------------
#define B_    8
#define S_    1024
#define D_    1024
#define H_    16
#define DH_   64
#define FF_   4096
#define TOK   (B_ * S_)
#define MTILES (TOK / 128)          // 64 M-tiles in every GEMM

// ---------------------------------------------------------------------------
// Scratch. bf16 operand buffers stored TILED: 16KB tiles (128 rows x 64 cols,
// SW128 swizzle pre-applied), tile index (row>>7)*(K>>6) + (col>>6).
// ---------------------------------------------------------------------------
__device__ float g_qkv[(size_t)TOK * 3 * D_];
__device__ float g_x2 [(size_t)TOK * D_];
__device__ __align__(1024) __nv_bfloat16 g_act_hi[(size_t)TOK * D_];
__device__ __align__(1024) __nv_bfloat16 g_act_lo[(size_t)TOK * D_];
__device__ __align__(1024) __nv_bfloat16 g_big_hi[(size_t)TOK * FF_];
__device__ __align__(1024) __nv_bfloat16 g_big_lo[(size_t)TOK * FF_];
__device__ __align__(1024) __nv_bfloat16 g_wqkv_h[(size_t)3 * D_ * D_];
__device__ __align__(1024) __nv_bfloat16 g_wqkv_l[(size_t)3 * D_ * D_];
__device__ __align__(1024) __nv_bfloat16 g_wo_h[(size_t)D_ * D_];
__device__ __align__(1024) __nv_bfloat16 g_wo_l[(size_t)D_ * D_];
__device__ __align__(1024) __nv_bfloat16 g_w1_h[(size_t)FF_ * D_];
__device__ __align__(1024) __nv_bfloat16 g_w1_l[(size_t)FF_ * D_];
__device__ __align__(1024) __nv_bfloat16 g_w2_h[(size_t)D_ * FF_];
__device__ __align__(1024) __nv_bfloat16 g_w2_l[(size_t)D_ * FF_];

// ---------------------------------------------------------------------------
// Tiled-layout addressing (portable)
// ---------------------------------------------------------------------------
__device__ __forceinline__ uint32_t sw128(uint32_t off) { return off ^ ((off >> 3) & 0x70); }

__device__ __forceinline__ size_t tiled_off(int row, int col, int Kk) {
    const int tr = row >> 7, tk = col >> 6;
    const uint32_t inb = ((uint32_t)(row & 127) << 7) | ((uint32_t)(col & 63) << 1);
    return (((size_t)tr * (size_t)(Kk >> 6) + (size_t)tk) << 14) + sw128(inb);
}

// ---------------------------------------------------------------------------
// PTX helpers
// ---------------------------------------------------------------------------
#if HAS_TCGEN05
__device__ __forceinline__ uint32_t smem_u32_of(const void* p) {
    uint32_t a;
    asm("{ .reg .u64 t; cvta.to.shared.u64 t, %1; cvt.u32.u64 %0, t; }" : "=r"(a) : "l"(p));
    return a;
}
__device__ __forceinline__ void tma_bulk(uint32_t dst, const void* src, uint32_t bytes,
                                         uint32_t mbar) {
    asm volatile(
        "cp.async.bulk.shared::cta.global.mbarrier::complete_tx::bytes [%0], [%1], %2, [%3];"
        :: "r"(dst), "l"(src), "r"(bytes), "r"(mbar) : "memory");
}
__device__ __forceinline__ void mbar_expect_tx(uint32_t mbar, uint32_t bytes) {
    asm volatile("mbarrier.arrive.expect_tx.shared.b64 _, [%0], %1;"
                 :: "r"(mbar), "r"(bytes) : "memory");
}
__device__ __forceinline__ void mbar_arrive(uint32_t addr) {
    asm volatile("mbarrier.arrive.shared.b64 _, [%0];" :: "r"(addr) : "memory");
}

__device__ __forceinline__ uint64_t smem_desc(uint32_t addr) {
    constexpr uint64_t BASE = (uint64_t(2) << 61)   // SW128
                            | (uint64_t(1) << 46)   // Blackwell
                            | (uint64_t(64) << 32)  // SBO = 64
                            | (uint64_t(1) << 16);  // LBO = 1
    return BASE | ((uint64_t)(addr >> 4) & 0x3FFF);
}
// idesc cg1 kind::f16: d=f32, a=bf16, b=bf16, M=128, N=256
#define GEMM_IDESC ((1u<<4) | (1u<<7) | (1u<<10) | ((256u/8)<<17) | ((128u/16)<<24))

__device__ __forceinline__ void mma_f16_ss(uint32_t d, uint64_t a, uint64_t b,
                                           uint32_t idesc, bool acc) {
    uint32_t e = acc ? 1u : 0u;
    asm volatile(
        "{\n\t.reg .pred p;\n\t"
        "setp.ne.u32 p, %4, 0;\n\t"
        "tcgen05.mma.cta_group::1.kind::f16 [%0], %1, %2, %3, {%5, %5, %5, %5}, p;\n\t}"
        :: "r"(d), "l"(a), "l"(b), "r"(idesc), "r"(e), "r"(0u) : "memory");
}
__device__ __forceinline__ void mbar_init(uint32_t addr, uint32_t cnt) {
    asm volatile("mbarrier.init.shared.b64 [%0], %1;" :: "r"(addr), "r"(cnt) : "memory");
}
__device__ __forceinline__ void mbar_wait(uint32_t addr, uint32_t parity) {
    asm volatile(
        "{\n\t.reg .pred P;\n\t"
        "W%=:\n\t"
        "mbarrier.try_wait.parity.acquire.cta.shared::cta.b64 P, [%0], %1, 0x989680;\n\t"
        "@!P bra W%=;\n\t}"
        :: "r"(addr), "r"(parity) : "memory");
}

#define TC_ALLOC(sm, n)   asm volatile("tcgen05.alloc.cta_group::1.sync.aligned.shared::cta.b32 [%0], %1;" :: "r"(sm), "r"(n) : "memory")
#define TC_RELINQ()       asm volatile("tcgen05.relinquish_alloc_permit.cta_group::1.sync.aligned;")
#define TC_DEALLOC(t, n)  asm volatile("tcgen05.dealloc.cta_group::1.sync.aligned.b32 %0, %1;" :: "r"(t), "r"(n))
#define TC_COMMIT(mb)     asm volatile("tcgen05.commit.cta_group::1.mbarrier::arrive::one.shared::cluster.b64 [%0];" :: "r"(mb) : "memory")
#define TC_FENCE_AFTER()  asm volatile("tcgen05.fence::after_thread_sync;" ::: "memory")
#define TC_FENCE_BEFORE() asm volatile("tcgen05.fence::before_thread_sync;" ::: "memory")
#define TC_WAIT_LD()      asm volatile("tcgen05.wait::ld.sync.aligned;" ::: "memory")

#define TC_LD_X32(r, t) \
    asm volatile( \
        "tcgen05.ld.sync.aligned.32x32b.x32.b32 " \
        "{%0, %1, %2, %3, %4, %5, %6, %7, " \
        " %8, %9, %10, %11, %12, %13, %14, %15, " \
        " %16, %17, %18, %19, %20, %21, %22, %23, " \
        " %24, %25, %26, %27, %28, %29, %30, %31}, [%32];" \
        : "=r"((r)[0]),  "=r"((r)[1]),  "=r"((r)[2]),  "=r"((r)[3]), \
          "=r"((r)[4]),  "=r"((r)[5]),  "=r"((r)[6]),  "=r"((r)[7]), \
          "=r"((r)[8]),  "=r"((r)[9]),  "=r"((r)[10]), "=r"((r)[11]), \
          "=r"((r)[12]), "=r"((r)[13]), "=r"((r)[14]), "=r"((r)[15]), \
          "=r"((r)[16]), "=r"((r)[17]), "=r"((r)[18]), "=r"((r)[19]), \
          "=r"((r)[20]), "=r"((r)[21]), "=r"((r)[22]), "=r"((r)[23]), \
          "=r"((r)[24]), "=r"((r)[25]), "=r"((r)[26]), "=r"((r)[27]), \
          "=r"((r)[28]), "=r"((r)[29]), "=r"((r)[30]), "=r"((r)[31]) \
        : "r"(t))

// ---- packed f32x2 (Blackwell) ----
__device__ __forceinline__ uint64_t pack2f(float lo, float hi) {
    uint64_t r;
    asm("mov.b64 %0, {%1, %2};" : "=l"(r) : "f"(lo), "f"(hi));
    return r;
}
__device__ __forceinline__ void unpack2f(uint64_t v, float& lo, float& hi) {
    asm("mov.b64 {%0, %1}, %2;" : "=f"(lo), "=f"(hi) : "l"(v));
}
__device__ __forceinline__ void ffma2(uint64_t& d, uint64_t a, uint64_t b) {
    asm("fma.rn.f32x2 %0, %1, %2, %3;" : "=l"(d) : "l"(a), "l"(b), "l"(d));
}
__device__ __forceinline__ void fadd2(uint64_t& d, uint64_t a) {
    asm("add.rn.f32x2 %0, %1, %2;" : "=l"(d) : "l"(d), "l"(a));
}
__device__ __forceinline__ void fmul2(uint64_t& d, uint64_t a) {
    asm("mul.rn.f32x2 %0, %1, %2;" : "=l"(d) : "l"(d), "l"(a));
}
#endif  // HAS_TCGEN05

// ---------------------------------------------------------------------------
// fp32 -> bf16 (hi, lo) split store into TILED buffers
// ---------------------------------------------------------------------------
__device__ __forceinline__ void split_store4_tiled(__nv_bfloat16* __restrict__ hi,
                                                   __nv_bfloat16* __restrict__ lo,
                                                   int row, int col, int Kk, float4 v) {
    const size_t off = tiled_off(row, col, Kk);
    __nv_bfloat16 h0 = __float2bfloat16(v.x);
    __nv_bfloat16 h1 = __float2bfloat16(v.y);
    __nv_bfloat16 h2 = __float2bfloat16(v.z);
    __nv_bfloat16 h3 = __float2bfloat16(v.w);
    __nv_bfloat16 l0 = __float2bfloat16(v.x - __bfloat162float(h0));
    __nv_bfloat16 l1 = __float2bfloat16(v.y - __bfloat162float(h1));
    __nv_bfloat16 l2 = __float2bfloat16(v.z - __bfloat162float(h2));
    __nv_bfloat16 l3 = __float2bfloat16(v.w - __bfloat162float(h3));
    __nv_bfloat162 ha; ha.x = h0; ha.y = h1;
    __nv_bfloat162 hb; hb.x = h2; hb.y = h3;
    __nv_bfloat162 la; la.x = l0; la.y = l1;
    __nv_bfloat162 lb; lb.x = l2; lb.y = l3;
    *(__nv_bfloat162*)((char*)hi + off)     = ha;
    *(__nv_bfloat162*)((char*)hi + off + 4) = hb;
    *(__nv_bfloat162*)((char*)lo + off)     = la;
    *(__nv_bfloat162*)((char*)lo + off + 4) = lb;
}

__global__ __launch_bounds__(256)
void split_kernel(const float* __restrict__ x,
                  __nv_bfloat16* __restrict__ hi,
                  __nv_bfloat16* __restrict__ lo, int n4, int K)
{
    int i = blockIdx.x * 256 + threadIdx.x;
    if (i < n4) {
        float4 v = ((const float4*)x)[i];
        const int e = i << 2;
        split_store4_tiled(hi, lo, e / K, e % K, K, v);
    }
}

// ---------------------------------------------------------------------------
// LayerNorm fused with tiled bf16 split output
// ---------------------------------------------------------------------------
__global__ __launch_bounds__(256)
void ln_split_kernel(const float* __restrict__ x,
                     const float* __restrict__ gw,
                     const float* __restrict__ bw,
                     __nv_bfloat16* __restrict__ out_hi,
                     __nv_bfloat16* __restrict__ out_lo)
{
    __shared__ float red[16];
    const int row = blockIdx.x;
    const int tid = threadIdx.x;

    const float4 v = ((const float4*)(x + (size_t)row * D_))[tid];
    float s  = v.x + v.y + v.z + v.w;
    float ss = v.x*v.x + v.y*v.y + v.z*v.z + v.w*v.w;

    #pragma unroll
    for (int o = 16; o; o >>= 1) {
        s  += __shfl_xor_sync(0xffffffffu, s,  o);
        ss += __shfl_xor_sync(0xffffffffu, ss, o);
    }
    const int wid = tid >> 5, lid = tid & 31;
    if (lid == 0) { red[wid] = s; red[8 + wid] = ss; }
    __syncthreads();

    float sum = 0.f, sq = 0.f;
    #pragma unroll
    for (int i = 0; i < 8; i++) { sum += red[i]; sq += red[8 + i]; }

    const float mu  = sum * (1.0f / D_);
    const float var = sq  * (1.0f / D_) - mu * mu;
    const float rs  = rsqrtf(var + 1e-5f);

    const float4 g4 = ((const float4*)gw)[tid];
    const float4 b4 = ((const float4*)bw)[tid];
    float4 o;
    o.x = (v.x - mu) * rs * g4.x + b4.x;
    o.y = (v.y - mu) * rs * g4.y + b4.y;
    o.z = (v.z - mu) * rs * g4.z + b4.z;
    o.w = (v.w - mu) * rs * g4.w + b4.w;
    split_store4_tiled(out_hi, out_lo, row, tid * 4, D_, o);
}

// ---------------------------------------------------------------------------
// PERSISTENT GEMM (TN), cg1 tcgen05 128x256 tile, TMA bulk, 2x96KB ring,
// TMEM double-buffered (2 x 256 cols). 320 threads:
//   tid 0..255 (warps 0-7): epilogue per tile
//   tid 256 (warp 8 lane 0): MMA issuer
//   tid 288 (warp 9 lane 0): TMA producer (stage ring runs across tiles)
//   tids 257-287, 289-319: idle (skip to terminal sync) — MUST NOT enter the
//   epilogue (partial-warp tcgen05.ld + epi over-arrival caused the R15 hang).
// ---------------------------------------------------------------------------
enum { EPI_BIAS = 0, EPI_BIAS_RES = 1, EPI_GELU_SPLIT = 2 };

__device__ __forceinline__ float gelu_tanh(float x)
{
    const float u = 0.7978845608028654f * (x + 0.044715f * x * x * x);
    return 0.5f * x * (1.0f + tanhf(u));
}

#define STAGE_BYTES 98304
#define SMEM_GEMM   (1024 + 2 * STAGE_BYTES)
#define GEMM_GRID   148

template <int EPI>
__global__ __launch_bounds__(320, 1)
void gemm_tc(const __nv_bfloat16* __restrict__ Ah, const __nv_bfloat16* __restrict__ Al,
             const __nv_bfloat16* __restrict__ Bh, const __nv_bfloat16* __restrict__ Bl,
             const float* __restrict__ bias, const float* __restrict__ resid,
             float* __restrict__ Cf,
             __nv_bfloat16* __restrict__ Chi, __nv_bfloat16* __restrict__ Clo,
             int N, int K)
{
#if HAS_TCGEN05
    extern __shared__ char smem[];
    const uint32_t sm = smem_u32_of(smem);
    const int tid = threadIdx.x;
    const int wid = tid >> 5;
    const int lid = tid & 31;
    const int KT  = K >> 6;                     // stages per tile
    const int ntiles = MTILES * (N >> 8);       // total tiles this GEMM
    const int bid = blockIdx.x;

    // barriers: done[s] sm+8+8s (count1); full[s] sm+24+8s (count1, tx);
    //           fin[b] sm+40+8b (count1); epi[b] sm+56+8b (count 256)
    if (tid == 0) {
        mbar_init(sm + 8,  1);   mbar_init(sm + 16, 1);
        mbar_init(sm + 24, 1);   mbar_init(sm + 32, 1);
        mbar_init(sm + 40, 1);   mbar_init(sm + 48, 1);
        mbar_init(sm + 56, 256); mbar_init(sm + 64, 256);
    }
    if (wid == 0) {
        TC_ALLOC(sm, 512);       // two 256-col accumulator buffers
        TC_RELINQ();
    }
    __syncthreads();

    uint32_t tmem;
    asm volatile("ld.shared.b32 %0, [%1];" : "=r"(tmem) : "r"(sm));

    if (tid == 288) {
        // ------------------- TMA producer (persistent) ----------------------
        const char* pAh = (const char*)Ah;
        const char* pAl = (const char*)Al;
        const char* pBh = (const char*)Bh;
        const char* pBl = (const char*)Bl;
        int ss = 0;                              // stage counter across tiles
        for (int tile = bid; tile < ntiles; tile += GEMM_GRID) {
            const int mb  = tile % MTILES;
            const int nb0 = (tile / MTILES) * 2;
            for (int t = 0; t < KT; ++t, ++ss) {
                const int s = ss & 1;
                if (ss >= 2) mbar_wait(sm + 8 + s * 8, ((ss >> 1) - 1) & 1);
                const uint32_t sb = sm + 1024 + s * STAGE_BYTES;
                const uint32_t fb = sm + 24 + s * 8;
                mbar_expect_tx(fb, STAGE_BYTES);
                const size_t aoff = ((size_t)(mb * KT + t)) << 14;
                const size_t b0   = ((size_t)(nb0 * KT + t)) << 14;
                const size_t b1   = ((size_t)((nb0 + 1) * KT + t)) << 14;
                tma_bulk(sb,         pAh + aoff, 16384, fb);
                tma_bulk(sb + 16384, pAl + aoff, 16384, fb);
                tma_bulk(sb + 32768, pBh + b0,   16384, fb);
                tma_bulk(sb + 49152, pBh + b1,   16384, fb);
                tma_bulk(sb + 65536, pBl + b0,   16384, fb);
                tma_bulk(sb + 81920, pBl + b1,   16384, fb);
            }
        }
    } else if (tid == 256) {
        // ------------------- MMA issuer (persistent) ------------------------
        uint64_t dAh[2], dAl[2], dBh[2], dBl[2];
        #pragma unroll
        for (int s = 0; s < 2; s++) {
            const uint32_t sb = sm + 1024 + s * STAGE_BYTES;
            dAh[s] = smem_desc(sb);
            dAl[s] = smem_desc(sb + 16384);
            dBh[s] = smem_desc(sb + 32768);
            dBl[s] = smem_desc(sb + 65536);
        }
        int ss = 0;
        int k = 0;
        for (int tile = bid; tile < ntiles; tile += GEMM_GRID, k++) {
            const int b = k & 1;
            // buffer b was read by the epilogue of local tile k-2: wait epi[b]
            if (k >= 2) mbar_wait(sm + 56 + b * 8, ((k >> 1) - 1) & 1);
            const uint32_t dbuf = tmem + b * 256;
            for (int t = 0; t < KT; ++t, ++ss) {
                const int s = ss & 1;
                mbar_wait(sm + 24 + s * 8, (ss >> 1) & 1);   // full[s]
                #pragma unroll
                for (int ks = 0; ks < 4; ks++) {
                    mma_f16_ss(dbuf, dAh[s] + ks*2, dBh[s] + ks*2, GEMM_IDESC, !(t == 0 && ks == 0));
                    mma_f16_ss(dbuf, dAh[s] + ks*2, dBl[s] + ks*2, GEMM_IDESC, true);
                    mma_f16_ss(dbuf, dAl[s] + ks*2, dBh[s] + ks*2, GEMM_IDESC, true);
                }
                TC_COMMIT(sm + 8 + s * 8);                   // done[s]
            }
            TC_COMMIT(sm + 40 + b * 8);                      // fin[b]: tile k done
        }
    } else if (tid < 256) {
        // ------------------- epilogue warps (persistent) --------------------
        int k = 0;
        for (int tile = bid; tile < ntiles; tile += GEMM_GRID, k++) {
            const int b = k & 1;
            mbar_wait(sm + 40 + b * 8, (k >> 1) & 1);        // fin[b]
            TC_FENCE_AFTER();
            const int mb  = tile % MTILES;
            const int n0  = (tile / MTILES) << 8;
            const int m   = (mb << 7) + (wid & 3) * 32 + lid;
            const int cb0 = (wid >> 2) * 4;
            const uint32_t dbuf = tmem + b * 256;
            #pragma unroll
            for (int cc = 0; cc < 4; cc++) {
                const int cb = cb0 + cc;
                uint32_t dr[32];
                TC_LD_X32(dr, dbuf + cb * 32);
                TC_WAIT_LD();
                const int nb = n0 + cb * 32;
                if (EPI == EPI_GELU_SPLIT) {
                    #pragma unroll
                    for (int j = 0; j < 32; j += 4) {
                        float4 v;
                        v.x = gelu_tanh(__uint_as_float(dr[j])     + bias[nb + j]);
                        v.y = gelu_tanh(__uint_as_float(dr[j + 1]) + bias[nb + j + 1]);
                        v.z = gelu_tanh(__uint_as_float(dr[j + 2]) + bias[nb + j + 2]);
                        v.w = gelu_tanh(__uint_as_float(dr[j + 3]) + bias[nb + j + 3]);
                        split_store4_tiled(Chi, Clo, m, nb + j, N, v);
                    }
                } else {
                    #pragma unroll
                    for (int j = 0; j < 32; j += 4) {
                        float4 v;
                        v.x = __uint_as_float(dr[j])     + bias[nb + j];
                        v.y = __uint_as_float(dr[j + 1]) + bias[nb + j + 1];
                        v.z = __uint_as_float(dr[j + 2]) + bias[nb + j + 2];
                        v.w = __uint_as_float(dr[j + 3]) + bias[nb + j + 3];
                        if (EPI == EPI_BIAS_RES) {
                            const float4 rr = *(const float4*)(resid + (size_t)m * N + nb + j);
                            v.x += rr.x; v.y += rr.y; v.z += rr.z; v.w += rr.w;
                        }
                        *(float4*)(Cf + (size_t)m * N + nb + j) = v;
                    }
                }
            }
            TC_FENCE_BEFORE();
            mbar_arrive(sm + 56 + b * 8);                    // epi[b]
        }
    }
    // tids 257-287, 289-319: no work; fall through to terminal sync

    __syncthreads();
    if (wid == 0) TC_DEALLOC(tmem, 512);

#else  // ------------------- portable SIMT fallback (persistent) -----------
    extern __shared__ char smem[];
    float* As = (float*)smem;
    float* Bs = (float*)(smem + 16 * 128 * 4);
    const int tid = threadIdx.x;
    const int ntiles = MTILES * (N >> 8);
    const int ty = tid >> 4;
    const int tx = tid & 15;
    const bool act = (tid < 256);

    for (int tile = blockIdx.x; tile < ntiles; tile += GEMM_GRID) {
        const int m0 = (tile % MTILES) * 128;
        const int nb = (tile / MTILES) * 256;
        for (int nh = 0; nh < 2; nh++) {
            const int n0 = nb + nh * 128;
            float acc[8][8];
            #pragma unroll
            for (int i = 0; i < 8; i++)
                #pragma unroll
                for (int j = 0; j < 8; j++) acc[i][j] = 0.f;

            for (int k0 = 0; k0 < K; k0 += 16) {
                __syncthreads();
                for (int i = tid; i < 2048; i += 320) {
                    const int r = i >> 4, c = i & 15;
                    const size_t oa = tiled_off(m0 + r, k0 + c, K);
                    As[c * 128 + r] =
                        __bfloat162float(*(const __nv_bfloat16*)((const char*)Ah + oa)) +
                        __bfloat162float(*(const __nv_bfloat16*)((const char*)Al + oa));
                    const size_t ob = tiled_off(n0 + r, k0 + c, K);
                    Bs[c * 128 + r] =
                        __bfloat162float(*(const __nv_bfloat16*)((const char*)Bh + ob)) +
                        __bfloat162float(*(const __nv_bfloat16*)((const char*)Bl + ob));
                }
                __syncthreads();
                if (act) {
                    #pragma unroll
                    for (int kk = 0; kk < 16; kk++) {
                        float a[8], b[8];
                        #pragma unroll
                        for (int i = 0; i < 8; i++) a[i] = As[kk * 128 + ty * 8 + i];
                        #pragma unroll
                        for (int j = 0; j < 8; j++) b[j] = Bs[kk * 128 + tx * 8 + j];
                        #pragma unroll
                        for (int i = 0; i < 8; i++)
                            #pragma unroll
                            for (int j = 0; j < 8; j++)
                                acc[i][j] = fmaf(a[i], b[j], acc[i][j]);
                    }
                }
            }

            if (act) {
                #pragma unroll
                for (int i = 0; i < 8; i++) {
                    const int m = m0 + ty * 8 + i;
                    #pragma unroll
                    for (int j = 0; j < 8; j++) {
                        const int n = n0 + tx * 8 + j;
                        float v = acc[i][j] + bias[n];
                        if (EPI == EPI_GELU_SPLIT) {
                            v = gelu_tanh(v);
                            __nv_bfloat16 hv = __float2bfloat16(v);
                            const size_t oc = tiled_off(m, n, N);
                            *(__nv_bfloat16*)((char*)Chi + oc) = hv;
                            *(__nv_bfloat16*)((char*)Clo + oc) =
                                __float2bfloat16(v - __bfloat162float(hv));
                        } else {
                            if (EPI == EPI_BIAS_RES) v += resid[(size_t)m * N + n];
                            Cf[(size_t)m * N + n] = v;
                        }
                    }
                }
            }
            __syncthreads();
        }
    }
#endif
}

// ---------------------------------------------------------------------------
// Causal flash attention: 128 queries/block, 1 thread per query, 64-key K/V
// tiles in smem, packed f32x2 FMA inner loops. Output: tiled bf16 split.
// ---------------------------------------------------------------------------
__global__ __launch_bounds__(128)
void attn_kernel(const float* __restrict__ qkv,
                 __nv_bfloat16* __restrict__ out_hi,
                 __nv_bfloat16* __restrict__ out_lo)
{
    __shared__ float k_s[64][68];
    __shared__ float v_s[64][64];

    const int qt = blockIdx.x;
    const int bh = blockIdx.y;
    const int b  = bh >> 4;
    const int h  = bh & 15;
    const int t  = threadIdx.x;
    const int g  = qt * 128 + t;

    const size_t seq_base = (size_t)b * S_ * (3 * D_);
    const size_t head_off = (size_t)h * DH_;
    const int numkt = 2 * qt + 2;
    const int orow = b * S_ + g;

#if HAS_TCGEN05
    uint64_t qp[32];
    {
        const ulonglong2* q128 = (const ulonglong2*)(qkv + seq_base + head_off +
                                                     (size_t)g * (3 * D_));
        #pragma unroll
        for (int i = 0; i < 16; i++) {
            const ulonglong2 u = q128[i];
            qp[2*i] = u.x; qp[2*i+1] = u.y;
        }
    }
    uint64_t op[32];
    #pragma unroll
    for (int i = 0; i < 32; i++) op[i] = 0ull;
    float m = -1e30f, l = 0.f;

    for (int kt = 0; kt < numkt; kt++) {
        const float* kp = qkv + seq_base + D_     + head_off + (size_t)(kt * 64) * (3 * D_);
        const float* vp = qkv + seq_base + 2 * D_ + head_off + (size_t)(kt * 64) * (3 * D_);
        #pragma unroll 4
        for (int i = t; i < 64 * 16; i += 128) {
            const int r = i >> 4;
            const int c = (i & 15) << 2;
            *(float4*)&k_s[r][c] = *(const float4*)(kp + (size_t)r * (3 * D_) + c);
            *(float4*)&v_s[r][c] = *(const float4*)(vp + (size_t)r * (3 * D_) + c);
        }
        __syncthreads();

        const bool edge = (kt >= 2 * qt);
        #pragma unroll
        for (int half = 0; half < 2; half++) {
            const int kbase = half * 32;
            float s[32];
            float mt = -1e30f;
            #pragma unroll 2
            for (int kc = 0; kc < 32; kc++) {
                const ulonglong2* krow = (const ulonglong2*)k_s[kbase + kc];
                uint64_t a0 = 0ull, a1 = 0ull, a2 = 0ull, a3 = 0ull;
                #pragma unroll
                for (int i = 0; i < 8; i++) {
                    const ulonglong2 u0 = krow[2*i];
                    const ulonglong2 u1 = krow[2*i+1];
                    ffma2(a0, qp[4*i],   u0.x);
                    ffma2(a1, qp[4*i+1], u0.y);
                    ffma2(a2, qp[4*i+2], u1.x);
                    ffma2(a3, qp[4*i+3], u1.y);
                }
                fadd2(a0, a2); fadd2(a1, a3); fadd2(a0, a1);
                float lo, hi; unpack2f(a0, lo, hi);
                float sc = (lo + hi) * 0.125f;
                if (edge && (kt * 64 + kbase + kc) > g) sc = -1e30f;
                s[kc] = sc;
                mt = fmaxf(mt, sc);
            }
            const float m_new = fmaxf(m, mt);
            const float corr  = __expf(m - m_new);
            l *= corr;
            const uint64_t corr2 = pack2f(corr, corr);
            #pragma unroll
            for (int i = 0; i < 32; i++) fmul2(op[i], corr2);
            #pragma unroll 2
            for (int kc = 0; kc < 32; kc++) {
                const float p = __expf(s[kc] - m_new);
                l += p;
                const uint64_t p2 = pack2f(p, p);
                const ulonglong2* vrow = (const ulonglong2*)v_s[kbase + kc];
                #pragma unroll
                for (int i = 0; i < 16; i++) {
                    const ulonglong2 u = vrow[i];
                    ffma2(op[2*i],   p2, u.x);
                    ffma2(op[2*i+1], p2, u.y);
                }
            }
            m = m_new;
        }
        __syncthreads();
    }

    const float inv_l = 1.0f / l;
    #pragma unroll
    for (int i = 0; i < 16; i++) {
        float4 v;
        unpack2f(op[2*i],   v.x, v.y);
        unpack2f(op[2*i+1], v.z, v.w);
        v.x *= inv_l; v.y *= inv_l; v.z *= inv_l; v.w *= inv_l;
        split_store4_tiled(out_hi, out_lo, orow, (int)head_off + i * 4, D_, v);
    }

#else
    float q[64];
    {
        const float* qpt = qkv + seq_base + head_off + (size_t)g * (3 * D_);
        #pragma unroll
        for (int d = 0; d < 64; d += 4) {
            const float4 u = *(const float4*)(qpt + d);
            q[d] = u.x; q[d+1] = u.y; q[d+2] = u.z; q[d+3] = u.w;
        }
    }
    float o[64];
    #pragma unroll
    for (int d = 0; d < 64; d++) o[d] = 0.f;
    float m = -1e30f, l = 0.f;

    for (int kt = 0; kt < numkt; kt++) {
        const float* kp = qkv + seq_base + D_     + head_off + (size_t)(kt * 64) * (3 * D_);
        const float* vp = qkv + seq_base + 2 * D_ + head_off + (size_t)(kt * 64) * (3 * D_);
        #pragma unroll 4
        for (int i = t; i < 64 * 16; i += 128) {
            const int r = i >> 4;
            const int c = (i & 15) << 2;
            *(float4*)&k_s[r][c] = *(const float4*)(kp + (size_t)r * (3 * D_) + c);
            *(float4*)&v_s[r][c] = *(const float4*)(vp + (size_t)r * (3 * D_) + c);
        }
        __syncthreads();

        const bool edge = (kt >= 2 * qt);
        #pragma unroll
        for (int half = 0; half < 2; half++) {
            const int kbase = half * 32;
            float s[32];
            float mt = -1e30f;
            #pragma unroll 2
            for (int kc = 0; kc < 32; kc++) {
                const float4* krow = (const float4*)k_s[kbase + kc];
                float d0 = 0.f, d1 = 0.f, d2 = 0.f, d3 = 0.f;
                #pragma unroll
                for (int d4 = 0; d4 < 16; d4++) {
                    const float4 kv = krow[d4];
                    d0 = fmaf(q[4*d4+0], kv.x, d0);
                    d1 = fmaf(q[4*d4+1], kv.y, d1);
                    d2 = fmaf(q[4*d4+2], kv.z, d2);
                    d3 = fmaf(q[4*d4+3], kv.w, d3);
                }
                float sc = (d0 + d1 + d2 + d3) * 0.125f;
                if (edge && (kt * 64 + kbase + kc) > g) sc = -1e30f;
                s[kc] = sc;
                mt = fmaxf(mt, sc);
            }
            const float m_new = fmaxf(m, mt);
            const float corr  = __expf(m - m_new);
            l *= corr;
            #pragma unroll
            for (int d = 0; d < 64; d++) o[d] *= corr;
            #pragma unroll 2
            for (int kc = 0; kc < 32; kc++) {
                const float p = __expf(s[kc] - m_new);
                l += p;
                const float4* vrow = (const float4*)v_s[kbase + kc];
                #pragma unroll
                for (int d4 = 0; d4 < 16; d4++) {
                    const float4 vv = vrow[d4];
                    o[4*d4+0] = fmaf(p, vv.x, o[4*d4+0]);
                    o[4*d4+1] = fmaf(p, vv.y, o[4*d4+1]);
                    o[4*d4+2] = fmaf(p, vv.z, o[4*d4+2]);
                    o[4*d4+3] = fmaf(p, vv.w, o[4*d4+3]);
                }
            }
            m = m_new;
        }
        __syncthreads();
    }

    const float inv_l = 1.0f / l;
    #pragma unroll
    for (int d4 = 0; d4 < 16; d4++) {
        float4 v;
        v.x = o[4*d4+0] * inv_l;
        v.y = o[4*d4+1] * inv_l;
        v.z = o[4*d4+2] * inv_l;
        v.w = o[4*d4+3] * inv_l;
        split_store4_tiled(out_hi, out_lo, orow, (int)head_off + d4 * 4, D_, v);
    }
#endif
}

// ---------------------------------------------------------------------------
// Launch
// ---------------------------------------------------------------------------
extern "C" void kernel_launch(void* const* d_in, const int* in_sizes, int n_in,
                              void* d_out, int out_size)
{
    const float* x     = (const float*)d_in[0];
    const float* ln1_g = (const float*)d_in[1];
    const float* ln1_b = (const float*)d_in[2];
    const float* w_qkv = (const float*)d_in[3];
    const float* b_qkv = (const float*)d_in[4];
    const float* w_o   = (const float*)d_in[5];
    const float* b_o   = (const float*)d_in[6];
    const float* ln2_g = (const float*)d_in[7];
    const float* ln2_b = (const float*)d_in[8];
    const float* w1    = (const float*)d_in[9];
    const float* b1    = (const float*)d_in[10];
    const float* w2    = (const float*)d_in[11];
    const float* b2    = (const float*)d_in[12];
    float* out = (float*)d_out;

    static bool inited = false;
    static float *p_qkv, *p_x2;
    static __nv_bfloat16 *p_act_h, *p_act_l, *p_big_h, *p_big_l;
    static __nv_bfloat16 *p_wqkv_h, *p_wqkv_l, *p_wo_h, *p_wo_l;
    static __nv_bfloat16 *p_w1_h, *p_w1_l, *p_w2_h, *p_w2_l;
    if (!inited) {
        void* p;
        cudaGetSymbolAddress(&p, g_qkv);    p_qkv    = (float*)p;
        cudaGetSymbolAddress(&p, g_x2);     p_x2     = (float*)p;
        cudaGetSymbolAddress(&p, g_act_hi); p_act_h  = (__nv_bfloat16*)p;
        cudaGetSymbolAddress(&p, g_act_lo); p_act_l  = (__nv_bfloat16*)p;
        cudaGetSymbolAddress(&p, g_big_hi); p_big_h  = (__nv_bfloat16*)p;
        cudaGetSymbolAddress(&p, g_big_lo); p_big_l  = (__nv_bfloat16*)p;
        cudaGetSymbolAddress(&p, g_wqkv_h); p_wqkv_h = (__nv_bfloat16*)p;
        cudaGetSymbolAddress(&p, g_wqkv_l); p_wqkv_l = (__nv_bfloat16*)p;
        cudaGetSymbolAddress(&p, g_wo_h);   p_wo_h   = (__nv_bfloat16*)p;
        cudaGetSymbolAddress(&p, g_wo_l);   p_wo_l   = (__nv_bfloat16*)p;
        cudaGetSymbolAddress(&p, g_w1_h);   p_w1_h   = (__nv_bfloat16*)p;
        cudaGetSymbolAddress(&p, g_w1_l);   p_w1_l   = (__nv_bfloat16*)p;
        cudaGetSymbolAddress(&p, g_w2_h);   p_w2_h   = (__nv_bfloat16*)p;
        cudaGetSymbolAddress(&p, g_w2_l);   p_w2_l   = (__nv_bfloat16*)p;
        cudaFuncSetAttribute(gemm_tc<EPI_BIAS>,       cudaFuncAttributeMaxDynamicSharedMemorySize, SMEM_GEMM);
        cudaFuncSetAttribute(gemm_tc<EPI_BIAS_RES>,   cudaFuncAttributeMaxDynamicSharedMemorySize, SMEM_GEMM);
        cudaFuncSetAttribute(gemm_tc<EPI_GELU_SPLIT>, cudaFuncAttributeMaxDynamicSharedMemorySize, SMEM_GEMM);
        inited = true;
    }

    // 0. weight splits -> tiled bf16 hi/lo
    split_kernel<<<(3*D_*D_/4 + 255)/256, 256>>>(w_qkv, p_wqkv_h, p_wqkv_l, 3*D_*D_/4, D_);
    split_kernel<<<(D_*D_/4   + 255)/256, 256>>>(w_o,   p_wo_h,   p_wo_l,   D_*D_/4,   D_);
    split_kernel<<<(FF_*D_/4  + 255)/256, 256>>>(w1,    p_w1_h,   p_w1_l,   FF_*D_/4,  D_);
    split_kernel<<<(D_*FF_/4  + 255)/256, 256>>>(w2,    p_w2_h,   p_w2_l,   D_*FF_/4,  FF_);

    // 1. LN1 + split (tiled)
    ln_split_kernel<<<TOK, 256>>>(x, ln1_g, ln1_b, p_act_h, p_act_l);

    // 2. QKV projection (persistent, 148 CTAs)
    gemm_tc<EPI_BIAS><<<GEMM_GRID, 320, SMEM_GEMM>>>(
        p_act_h, p_act_l, p_wqkv_h, p_wqkv_l, b_qkv, nullptr,
        p_qkv, nullptr, nullptr, 3*D_, D_);

    // 3. causal attention
    attn_kernel<<<dim3(S_/128, B_*H_), 128>>>(p_qkv, p_act_h, p_act_l);

    // 4. output projection + residual
    gemm_tc<EPI_BIAS_RES><<<GEMM_GRID, 320, SMEM_GEMM>>>(
        p_act_h, p_act_l, p_wo_h, p_wo_l, b_o, x,
        p_x2, nullptr, nullptr, D_, D_);

    // 5. LN2 + split (tiled)
    ln_split_kernel<<<TOK, 256>>>(p_x2, ln2_g, ln2_b, p_act_h, p_act_l);

    // 6. FFN up + GELU + split (tiled)
    gemm_tc<EPI_GELU_SPLIT><<<GEMM_GRID, 320, SMEM_GEMM>>>(
        p_act_h, p_act_l, p_w1_h, p_w1_l, b1, nullptr,
        nullptr, p_big_h, p_big_l, FF_, D_);

    // 7. FFN down + residual -> out
    gemm_tc<EPI_BIAS_RES><<<GEMM_GRID, 320, SMEM_GEMM>>>(
        p_big_h, p_big_l, p_w2_h, p_w2_l, b2, p_x2,
        out, nullptr, nullptr, D_, FF_);
}

// round 17
// speedup vs baseline: 1.0694x; 1.0353x over previous
#include <cuda_runtime.h>
#include <cuda_bf16.h>
#include <math.h>
#include <stdint.h>

// ---------------------------------------------------------------------------
// Per-compilation-pass feature detection (plain compute_103 pass gets fallback)
// ---------------------------------------------------------------------------
#if defined(__CUDA_ARCH__)
# if defined(__CUDA_ARCH_FEAT_SM103_ALL) || defined(__CUDA_ARCH_FEAT_SM100_ALL) || \
     (defined(__CUDA_ARCH_FAMILY_SPECIFIC__) && (__CUDA_ARCH_FAMILY_SPECIFIC__ >= 1000))
#  define HAS_TCGEN05 1
# else
#  define HAS_TCGEN05 0
# endif
#else
# define HAS_TCGEN05 0
#endif

// ---------------------------------------------------------------------------
// Problem constants
// ---------------------------------------------------------------------------
#define B_    8
#define S_    1024
#define D_    1024
#define H_    16
#define DH_   64
#define FF_   4096
#define TOK   (B_ * S_)
#define MTILES  (TOK / 128)        // 64 128-row tiles
#define MPAIRS  (TOK / 256)        // 32 256-row pair tiles

// ---------------------------------------------------------------------------
// Scratch. bf16 operand buffers stored TILED: 16KB tiles (128 rows x 64 cols,
// SW128 swizzle pre-applied), tile index (row>>7)*(K>>6) + (col>>6).
// ---------------------------------------------------------------------------
__device__ float g_qkv[(size_t)TOK * 3 * D_];
__device__ float g_x2 [(size_t)TOK * D_];
__device__ __align__(1024) __nv_bfloat16 g_act_hi[(size_t)TOK * D_];
__device__ __align__(1024) __nv_bfloat16 g_act_lo[(size_t)TOK * D_];
__device__ __align__(1024) __nv_bfloat16 g_big_hi[(size_t)TOK * FF_];
__device__ __align__(1024) __nv_bfloat16 g_big_lo[(size_t)TOK * FF_];
__device__ __align__(1024) __nv_bfloat16 g_wqkv_h[(size_t)3 * D_ * D_];
__device__ __align__(1024) __nv_bfloat16 g_wqkv_l[(size_t)3 * D_ * D_];
__device__ __align__(1024) __nv_bfloat16 g_wo_h[(size_t)D_ * D_];
__device__ __align__(1024) __nv_bfloat16 g_wo_l[(size_t)D_ * D_];
__device__ __align__(1024) __nv_bfloat16 g_w1_h[(size_t)FF_ * D_];
__device__ __align__(1024) __nv_bfloat16 g_w1_l[(size_t)FF_ * D_];
__device__ __align__(1024) __nv_bfloat16 g_w2_h[(size_t)D_ * FF_];
__device__ __align__(1024) __nv_bfloat16 g_w2_l[(size_t)D_ * FF_];

// ---------------------------------------------------------------------------
// Tiled-layout addressing (portable)
// ---------------------------------------------------------------------------
__device__ __forceinline__ uint32_t sw128(uint32_t off) { return off ^ ((off >> 3) & 0x70); }

__device__ __forceinline__ size_t tiled_off(int row, int col, int Kk) {
    const int tr = row >> 7, tk = col >> 6;
    const uint32_t inb = ((uint32_t)(row & 127) << 7) | ((uint32_t)(col & 63) << 1);
    return (((size_t)tr * (size_t)(Kk >> 6) + (size_t)tk) << 14) + sw128(inb);
}

// ---------------------------------------------------------------------------
// PTX helpers
// ---------------------------------------------------------------------------
#if HAS_TCGEN05
__device__ __forceinline__ uint32_t smem_u32_of(const void* p) {
    uint32_t a;
    asm("{ .reg .u64 t; cvta.to.shared.u64 t, %1; cvt.u32.u64 %0, t; }" : "=r"(a) : "l"(p));
    return a;
}
#define CLUSTER_SYNC() do { \
    asm volatile("barrier.cluster.arrive.aligned;" ::: "memory"); \
    asm volatile("barrier.cluster.wait.aligned;" ::: "memory"); \
} while (0)

__device__ __forceinline__ void tma_bulk(uint32_t dst, const void* src, uint32_t bytes,
                                         uint32_t mbar) {
    asm volatile(
        "cp.async.bulk.shared::cta.global.mbarrier::complete_tx::bytes [%0], [%1], %2, [%3];"
        :: "r"(dst), "l"(src), "r"(bytes), "r"(mbar) : "memory");
}
__device__ __forceinline__ void mbar_expect_tx(uint32_t mbar, uint32_t bytes) {
    asm volatile("mbarrier.arrive.expect_tx.shared.b64 _, [%0], %1;"
                 :: "r"(mbar), "r"(bytes) : "memory");
}
__device__ __forceinline__ void mbar_arrive(uint32_t addr) {
    asm volatile("mbarrier.arrive.shared.b64 _, [%0];" :: "r"(addr) : "memory");
}
// arrive on the mbarrier at the same SMEM offset in cluster CTA `rank`
__device__ __forceinline__ void mbar_arrive_cluster(uint32_t local_addr, uint32_t rank) {
    asm volatile(
        "{\n\t.reg .b32 r;\n\t"
        "mapa.shared::cluster.u32 r, %0, %1;\n\t"
        "mbarrier.arrive.shared::cluster.b64 _, [r];\n\t}"
        :: "r"(local_addr), "r"(rank) : "memory");
}

__device__ __forceinline__ uint64_t smem_desc(uint32_t addr) {
    constexpr uint64_t BASE = (uint64_t(2) << 61)   // SW128
                            | (uint64_t(1) << 46)   // Blackwell
                            | (uint64_t(64) << 32)  // SBO = 64
                            | (uint64_t(1) << 16);  // LBO = 1
    return BASE | ((uint64_t)(addr >> 4) & 0x3FFF);
}
// idesc cg2 kind::f16: d=f32, a=bf16, b=bf16, M_TOTAL=256, N=256
#define GEMM_IDESC2 ((1u<<4) | (1u<<7) | (1u<<10) | ((256u/8)<<17) | ((256u/16)<<24))

__device__ __forceinline__ void mma_f16_ss_cg2(uint32_t d, uint64_t a, uint64_t b,
                                               uint32_t idesc, bool acc) {
    uint32_t e = acc ? 1u : 0u;
    asm volatile(
        "{\n\t.reg .pred p;\n\t"
        "setp.ne.u32 p, %4, 0;\n\t"
        "tcgen05.mma.cta_group::2.kind::f16 [%0], %1, %2, %3, "
        "{%5, %5, %5, %5, %5, %5, %5, %5}, p;\n\t}"
        :: "r"(d), "l"(a), "l"(b), "r"(idesc), "r"(e), "r"(0u) : "memory");
}
__device__ __forceinline__ void mbar_init(uint32_t addr, uint32_t cnt) {
    asm volatile("mbarrier.init.shared.b64 [%0], %1;" :: "r"(addr), "r"(cnt) : "memory");
}
__device__ __forceinline__ void mbar_wait(uint32_t addr, uint32_t parity) {
    asm volatile(
        "{\n\t.reg .pred P;\n\t"
        "W%=:\n\t"
        "mbarrier.try_wait.parity.acquire.cta.shared::cta.b64 P, [%0], %1, 0x989680;\n\t"
        "@!P bra W%=;\n\t}"
        :: "r"(addr), "r"(parity) : "memory");
}

#define TC_ALLOC_CG2(sm, n)  asm volatile("tcgen05.alloc.cta_group::2.sync.aligned.shared::cta.b32 [%0], %1;" :: "r"(sm), "r"(n) : "memory")
#define TC_RELINQ_CG2()      asm volatile("tcgen05.relinquish_alloc_permit.cta_group::2.sync.aligned;")
#define TC_DEALLOC_CG2(t, n) asm volatile("tcgen05.dealloc.cta_group::2.sync.aligned.b32 %0, %1;" :: "r"(t), "r"(n))
#define TC_COMMIT_MC_CG2(mb, mask) \
    asm volatile("tcgen05.commit.cta_group::2.mbarrier::arrive::one.shared::cluster.multicast::cluster.b64 [%0], %1;" \
                 :: "r"(mb), "h"((uint16_t)(mask)) : "memory")
#define TC_FENCE_AFTER()  asm volatile("tcgen05.fence::after_thread_sync;" ::: "memory")
#define TC_FENCE_BEFORE() asm volatile("tcgen05.fence::before_thread_sync;" ::: "memory")
#define TC_WAIT_LD()      asm volatile("tcgen05.wait::ld.sync.aligned;" ::: "memory")

#define TC_LD_X32(r, t) \
    asm volatile( \
        "tcgen05.ld.sync.aligned.32x32b.x32.b32 " \
        "{%0, %1, %2, %3, %4, %5, %6, %7, " \
        " %8, %9, %10, %11, %12, %13, %14, %15, " \
        " %16, %17, %18, %19, %20, %21, %22, %23, " \
        " %24, %25, %26, %27, %28, %29, %30, %31}, [%32];" \
        : "=r"((r)[0]),  "=r"((r)[1]),  "=r"((r)[2]),  "=r"((r)[3]), \
          "=r"((r)[4]),  "=r"((r)[5]),  "=r"((r)[6]),  "=r"((r)[7]), \
          "=r"((r)[8]),  "=r"((r)[9]),  "=r"((r)[10]), "=r"((r)[11]), \
          "=r"((r)[12]), "=r"((r)[13]), "=r"((r)[14]), "=r"((r)[15]), \
          "=r"((r)[16]), "=r"((r)[17]), "=r"((r)[18]), "=r"((r)[19]), \
          "=r"((r)[20]), "=r"((r)[21]), "=r"((r)[22]), "=r"((r)[23]), \
          "=r"((r)[24]), "=r"((r)[25]), "=r"((r)[26]), "=r"((r)[27]), \
          "=r"((r)[28]), "=r"((r)[29]), "=r"((r)[30]), "=r"((r)[31]) \
        : "r"(t))

// ---- packed f32x2 (Blackwell) ----
__device__ __forceinline__ uint64_t pack2f(float lo, float hi) {
    uint64_t r;
    asm("mov.b64 %0, {%1, %2};" : "=l"(r) : "f"(lo), "f"(hi));
    return r;
}
__device__ __forceinline__ void unpack2f(uint64_t v, float& lo, float& hi) {
    asm("mov.b64 {%0, %1}, %2;" : "=f"(lo), "=f"(hi) : "l"(v));
}
__device__ __forceinline__ void ffma2(uint64_t& d, uint64_t a, uint64_t b) {
    asm("fma.rn.f32x2 %0, %1, %2, %3;" : "=l"(d) : "l"(a), "l"(b), "l"(d));
}
__device__ __forceinline__ void fadd2(uint64_t& d, uint64_t a) {
    asm("add.rn.f32x2 %0, %1, %2;" : "=l"(d) : "l"(d), "l"(a));
}
__device__ __forceinline__ void fmul2(uint64_t& d, uint64_t a) {
    asm("mul.rn.f32x2 %0, %1, %2;" : "=l"(d) : "l"(d), "l"(a));
}
#endif  // HAS_TCGEN05

// ---------------------------------------------------------------------------
// fp32 -> bf16 (hi, lo) split store into TILED buffers
// ---------------------------------------------------------------------------
__device__ __forceinline__ void split_store4_tiled(__nv_bfloat16* __restrict__ hi,
                                                   __nv_bfloat16* __restrict__ lo,
                                                   int row, int col, int Kk, float4 v) {
    const size_t off = tiled_off(row, col, Kk);
    __nv_bfloat16 h0 = __float2bfloat16(v.x);
    __nv_bfloat16 h1 = __float2bfloat16(v.y);
    __nv_bfloat16 h2 = __float2bfloat16(v.z);
    __nv_bfloat16 h3 = __float2bfloat16(v.w);
    __nv_bfloat16 l0 = __float2bfloat16(v.x - __bfloat162float(h0));
    __nv_bfloat16 l1 = __float2bfloat16(v.y - __bfloat162float(h1));
    __nv_bfloat16 l2 = __float2bfloat16(v.z - __bfloat162float(h2));
    __nv_bfloat16 l3 = __float2bfloat16(v.w - __bfloat162float(h3));
    __nv_bfloat162 ha; ha.x = h0; ha.y = h1;
    __nv_bfloat162 hb; hb.x = h2; hb.y = h3;
    __nv_bfloat162 la; la.x = l0; la.y = l1;
    __nv_bfloat162 lb; lb.x = l2; lb.y = l3;
    *(__nv_bfloat162*)((char*)hi + off)     = ha;
    *(__nv_bfloat162*)((char*)hi + off + 4) = hb;
    *(__nv_bfloat162*)((char*)lo + off)     = la;
    *(__nv_bfloat162*)((char*)lo + off + 4) = lb;
}

__global__ __launch_bounds__(256)
void split_kernel(const float* __restrict__ x,
                  __nv_bfloat16* __restrict__ hi,
                  __nv_bfloat16* __restrict__ lo, int n4, int K)
{
    int i = blockIdx.x * 256 + threadIdx.x;
    if (i < n4) {
        float4 v = ((const float4*)x)[i];
        const int e = i << 2;
        split_store4_tiled(hi, lo, e / K, e % K, K, v);
    }
}

// ---------------------------------------------------------------------------
// LayerNorm fused with tiled bf16 split output
// ---------------------------------------------------------------------------
__global__ __launch_bounds__(256)
void ln_split_kernel(const float* __restrict__ x,
                     const float* __restrict__ gw,
                     const float* __restrict__ bw,
                     __nv_bfloat16* __restrict__ out_hi,
                     __nv_bfloat16* __restrict__ out_lo)
{
    __shared__ float red[16];
    const int row = blockIdx.x;
    const int tid = threadIdx.x;

    const float4 v = ((const float4*)(x + (size_t)row * D_))[tid];
    float s  = v.x + v.y + v.z + v.w;
    float ss = v.x*v.x + v.y*v.y + v.z*v.z + v.w*v.w;

    #pragma unroll
    for (int o = 16; o; o >>= 1) {
        s  += __shfl_xor_sync(0xffffffffu, s,  o);
        ss += __shfl_xor_sync(0xffffffffu, ss, o);
    }
    const int wid = tid >> 5, lid = tid & 31;
    if (lid == 0) { red[wid] = s; red[8 + wid] = ss; }
    __syncthreads();

    float sum = 0.f, sq = 0.f;
    #pragma unroll
    for (int i = 0; i < 8; i++) { sum += red[i]; sq += red[8 + i]; }

    const float mu  = sum * (1.0f / D_);
    const float var = sq  * (1.0f / D_) - mu * mu;
    const float rs  = rsqrtf(var + 1e-5f);

    const float4 g4 = ((const float4*)gw)[tid];
    const float4 b4 = ((const float4*)bw)[tid];
    float4 o;
    o.x = (v.x - mu) * rs * g4.x + b4.x;
    o.y = (v.y - mu) * rs * g4.y + b4.y;
    o.z = (v.z - mu) * rs * g4.z + b4.z;
    o.w = (v.w - mu) * rs * g4.w + b4.w;
    split_store4_tiled(out_hi, out_lo, row, tid * 4, D_, o);
}

// ---------------------------------------------------------------------------
// PERSISTENT cg2 GEMM (TN): 74 clusters of 2 CTAs; pair tile M=256 x N=256,
// BK=64, 3 stages x 64KB/CTA; TMEM double-buffered (2 x 256 cols).
// 320 threads/CTA:
//   tid 0..255: epilogue (own 128 TMEM lanes per CTA)
//   tid 256: leader = MMA issuer; follower = full[] forwarder
//   tid 288: TMA producer (own A half + own B half)
//   tids 257-287, 289-319: idle (skip to terminal sync; NEVER enter epilogue)
// Barriers/CTA: done[s] sm+8+8s (cnt1, mc commit); full[s] sm+32+8s
//   (leader cnt2 = tx + fwd, follower cnt1 = tx); fin[b] sm+56+8b (cnt1, mc
//   commit); epi[b] sm+72+8b (leader cnt257 = 256 local + 1 fwd; follower
//   cnt256 local). All waits walked in order -> parity-safe.
// ---------------------------------------------------------------------------
enum { EPI_BIAS = 0, EPI_BIAS_RES = 1, EPI_GELU_SPLIT = 2 };

__device__ __forceinline__ float gelu_tanh(float x)
{
    const float u = 0.7978845608028654f * (x + 0.044715f * x * x * x);
    return 0.5f * x * (1.0f + tanhf(u));
}

#define STAGE_BYTES 65536
#define SMEM_GEMM   (1024 + 3 * STAGE_BYTES)
#define GEMM_GRID   148
#define NCLUSTERS   74

template <int EPI>
__global__ __launch_bounds__(320, 1) __cluster_dims__(2, 1, 1)
void gemm_tc(const __nv_bfloat16* __restrict__ Ah, const __nv_bfloat16* __restrict__ Al,
             const __nv_bfloat16* __restrict__ Bh, const __nv_bfloat16* __restrict__ Bl,
             const float* __restrict__ bias, const float* __restrict__ resid,
             float* __restrict__ Cf,
             __nv_bfloat16* __restrict__ Chi, __nv_bfloat16* __restrict__ Clo,
             int N, int K)
{
#if HAS_TCGEN05
    extern __shared__ char smem[];
    const uint32_t sm = smem_u32_of(smem);
    const int tid = threadIdx.x;
    const int wid = tid >> 5;
    const int lid = tid & 31;
    const int KT  = K >> 6;
    const int npairs = MPAIRS * (N >> 8);
    const int p0   = blockIdx.x >> 1;
    const int rank = blockIdx.x & 1;

    if (tid == 0) {
        mbar_init(sm + 8, 1);  mbar_init(sm + 16, 1);  mbar_init(sm + 24, 1);  // done[s]
        const uint32_t fcnt = (rank == 0) ? 2u : 1u;
        mbar_init(sm + 32, fcnt); mbar_init(sm + 40, fcnt); mbar_init(sm + 48, fcnt);
        mbar_init(sm + 56, 1);  mbar_init(sm + 64, 1);                         // fin[b]
        const uint32_t ecnt = (rank == 0) ? 257u : 256u;
        mbar_init(sm + 72, ecnt); mbar_init(sm + 80, ecnt);                    // epi[b]
    }
    if (wid == 0) {
        TC_ALLOC_CG2(sm, 512);
        TC_RELINQ_CG2();
    }
    __syncthreads();

    uint32_t tmem;
    asm volatile("ld.shared.b32 %0, [%1];" : "=r"(tmem) : "r"(sm));

    CLUSTER_SYNC();

    if (tid == 288) {
        // ------------------- TMA producer (persistent) ----------------------
        const char* pAh = (const char*)Ah;
        const char* pAl = (const char*)Al;
        const char* pBh = (const char*)Bh;
        const char* pBl = (const char*)Bl;
        int ss = 0;
        for (int pair = p0; pair < npairs; pair += NCLUSTERS) {
            const int mb2 = (pair % MPAIRS) * 2 + rank;      // 128-row A tile
            const int nb2 = (pair / MPAIRS) * 2 + rank;      // 128-row B tile
            for (int t = 0; t < KT; ++t, ++ss) {
                const int s = ss % 3;
                if (ss >= 3) mbar_wait(sm + 8 + s * 8, ((ss / 3) - 1) & 1);
                const uint32_t sb = sm + 1024 + s * STAGE_BYTES;
                const uint32_t fb = sm + 32 + s * 8;
                mbar_expect_tx(fb, STAGE_BYTES);
                const size_t aoff = ((size_t)(mb2 * KT + t)) << 14;
                const size_t boff = ((size_t)(nb2 * KT + t)) << 14;
                tma_bulk(sb,         pAh + aoff, 16384, fb);
                tma_bulk(sb + 16384, pAl + aoff, 16384, fb);
                tma_bulk(sb + 32768, pBh + boff, 16384, fb);
                tma_bulk(sb + 49152, pBl + boff, 16384, fb);
            }
        }
    } else if (tid == 256) {
        if (rank == 0) {
            // ------------------- MMA issuer (leader) ------------------------
            uint64_t dAh[3], dAl[3], dBh[3], dBl[3];
            #pragma unroll
            for (int s = 0; s < 3; s++) {
                const uint32_t sb = sm + 1024 + s * STAGE_BYTES;
                dAh[s] = smem_desc(sb);
                dAl[s] = smem_desc(sb + 16384);
                dBh[s] = smem_desc(sb + 32768);
                dBl[s] = smem_desc(sb + 49152);
            }
            int ss = 0, k = 0;
            for (int pair = p0; pair < npairs; pair += NCLUSTERS, k++) {
                const int b = k & 1;
                if (k >= 2) mbar_wait(sm + 72 + b * 8, ((k >> 1) - 1) & 1);  // epi[b]
                const uint32_t dbuf = tmem + b * 256;
                for (int t = 0; t < KT; ++t, ++ss) {
                    const int s = ss % 3;
                    mbar_wait(sm + 32 + s * 8, (ss / 3) & 1);                // full[s]
                    #pragma unroll
                    for (int ks = 0; ks < 4; ks++) {
                        mma_f16_ss_cg2(dbuf, dAh[s] + ks*2, dBh[s] + ks*2, GEMM_IDESC2,
                                       !(t == 0 && ks == 0));
                        mma_f16_ss_cg2(dbuf, dAh[s] + ks*2, dBl[s] + ks*2, GEMM_IDESC2, true);
                        mma_f16_ss_cg2(dbuf, dAl[s] + ks*2, dBh[s] + ks*2, GEMM_IDESC2, true);
                    }
                    TC_COMMIT_MC_CG2(sm + 8 + s * 8, 0x3);                   // done[s]
                }
                TC_COMMIT_MC_CG2(sm + 56 + b * 8, 0x3);                      // fin[b]
            }
        } else {
            // --------------- follower: forward tx-complete to leader --------
            int ss = 0;
            for (int pair = p0; pair < npairs; pair += NCLUSTERS) {
                for (int t = 0; t < KT; ++t, ++ss) {
                    const int s = ss % 3;
                    mbar_wait(sm + 32 + s * 8, (ss / 3) & 1);   // local full[s]
                    mbar_arrive_cluster(sm + 32 + s * 8, 0);    // leader full[s]
                }
            }
        }
    } else if (tid < 256) {
        // ------------------- epilogue warps (persistent) --------------------
        int k = 0;
        for (int pair = p0; pair < npairs; pair += NCLUSTERS, k++) {
            const int b = k & 1;
            mbar_wait(sm + 56 + b * 8, (k >> 1) & 1);           // fin[b]
            TC_FENCE_AFTER();
            const int m  = (pair % MPAIRS) * 256 + rank * 128 + (wid & 3) * 32 + lid;
            const int n0 = (pair / MPAIRS) << 8;
            const int cb0 = (wid >> 2) * 4;
            const uint32_t dbuf = tmem + b * 256;
            #pragma unroll
            for (int cc = 0; cc < 4; cc++) {
                const int cb = cb0 + cc;
                uint32_t dr[32];
                TC_LD_X32(dr, dbuf + cb * 32);
                TC_WAIT_LD();
                const int nb = n0 + cb * 32;
                if (EPI == EPI_GELU_SPLIT) {
                    #pragma unroll
                    for (int j = 0; j < 32; j += 4) {
                        float4 v;
                        v.x = gelu_tanh(__uint_as_float(dr[j])     + bias[nb + j]);
                        v.y = gelu_tanh(__uint_as_float(dr[j + 1]) + bias[nb + j + 1]);
                        v.z = gelu_tanh(__uint_as_float(dr[j + 2]) + bias[nb + j + 2]);
                        v.w = gelu_tanh(__uint_as_float(dr[j + 3]) + bias[nb + j + 3]);
                        split_store4_tiled(Chi, Clo, m, nb + j, N, v);
                    }
                } else {
                    #pragma unroll
                    for (int j = 0; j < 32; j += 4) {
                        float4 v;
                        v.x = __uint_as_float(dr[j])     + bias[nb + j];
                        v.y = __uint_as_float(dr[j + 1]) + bias[nb + j + 1];
                        v.z = __uint_as_float(dr[j + 2]) + bias[nb + j + 2];
                        v.w = __uint_as_float(dr[j + 3]) + bias[nb + j + 3];
                        if (EPI == EPI_BIAS_RES) {
                            const float4 rr = *(const float4*)(resid + (size_t)m * N + nb + j);
                            v.x += rr.x; v.y += rr.y; v.z += rr.z; v.w += rr.w;
                        }
                        *(float4*)(Cf + (size_t)m * N + nb + j) = v;
                    }
                }
            }
            TC_FENCE_BEFORE();
            // signal TMEM buffer release
            mbar_arrive(sm + 72 + b * 8);                       // local epi/epi_f
            if (rank == 1 && tid == 0) {
                // after all 256 local arrivals, forward one arrive to leader
                mbar_wait(sm + 72 + b * 8, (k >> 1) & 1);
                mbar_arrive_cluster(sm + 72 + b * 8, 0);
            }
        }
    }
    // tids 257-287, 289-319: no work

    __syncthreads();
    if (wid == 0) TC_DEALLOC_CG2(tmem, 512);
    CLUSTER_SYNC();

#else  // ------------------- portable SIMT fallback (persistent) -----------
    extern __shared__ char smem[];
    float* As = (float*)smem;
    float* Bs = (float*)(smem + 16 * 128 * 4);
    const int tid = threadIdx.x;
    const int ntiles = MTILES * (N >> 8);
    const int ty = tid >> 4;
    const int tx = tid & 15;
    const bool act = (tid < 256);

    for (int tile = blockIdx.x; tile < ntiles; tile += GEMM_GRID) {
        const int m0 = (tile % MTILES) * 128;
        const int nb = (tile / MTILES) * 256;
        for (int nh = 0; nh < 2; nh++) {
            const int n0 = nb + nh * 128;
            float acc[8][8];
            #pragma unroll
            for (int i = 0; i < 8; i++)
                #pragma unroll
                for (int j = 0; j < 8; j++) acc[i][j] = 0.f;

            for (int k0 = 0; k0 < K; k0 += 16) {
                __syncthreads();
                for (int i = tid; i < 2048; i += 320) {
                    const int r = i >> 4, c = i & 15;
                    const size_t oa = tiled_off(m0 + r, k0 + c, K);
                    As[c * 128 + r] =
                        __bfloat162float(*(const __nv_bfloat16*)((const char*)Ah + oa)) +
                        __bfloat162float(*(const __nv_bfloat16*)((const char*)Al + oa));
                    const size_t ob = tiled_off(n0 + r, k0 + c, K);
                    Bs[c * 128 + r] =
                        __bfloat162float(*(const __nv_bfloat16*)((const char*)Bh + ob)) +
                        __bfloat162float(*(const __nv_bfloat16*)((const char*)Bl + ob));
                }
                __syncthreads();
                if (act) {
                    #pragma unroll
                    for (int kk = 0; kk < 16; kk++) {
                        float a[8], b[8];
                        #pragma unroll
                        for (int i = 0; i < 8; i++) a[i] = As[kk * 128 + ty * 8 + i];
                        #pragma unroll
                        for (int j = 0; j < 8; j++) b[j] = Bs[kk * 128 + tx * 8 + j];
                        #pragma unroll
                        for (int i = 0; i < 8; i++)
                            #pragma unroll
                            for (int j = 0; j < 8; j++)
                                acc[i][j] = fmaf(a[i], b[j], acc[i][j]);
                    }
                }
            }

            if (act) {
                #pragma unroll
                for (int i = 0; i < 8; i++) {
                    const int m = m0 + ty * 8 + i;
                    #pragma unroll
                    for (int j = 0; j < 8; j++) {
                        const int n = n0 + tx * 8 + j;
                        float v = acc[i][j] + bias[n];
                        if (EPI == EPI_GELU_SPLIT) {
                            v = gelu_tanh(v);
                            __nv_bfloat16 hv = __float2bfloat16(v);
                            const size_t oc = tiled_off(m, n, N);
                            *(__nv_bfloat16*)((char*)Chi + oc) = hv;
                            *(__nv_bfloat16*)((char*)Clo + oc) =
                                __float2bfloat16(v - __bfloat162float(hv));
                        } else {
                            if (EPI == EPI_BIAS_RES) v += resid[(size_t)m * N + n];
                            Cf[(size_t)m * N + n] = v;
                        }
                    }
                }
            }
            __syncthreads();
        }
    }
#endif
}

// ---------------------------------------------------------------------------
// Causal flash attention: 128 queries/block, 1 thread per query, 64-key K/V
// tiles in smem, packed f32x2 FMA inner loops. Output: tiled bf16 split.
// ---------------------------------------------------------------------------
__global__ __launch_bounds__(128)
void attn_kernel(const float* __restrict__ qkv,
                 __nv_bfloat16* __restrict__ out_hi,
                 __nv_bfloat16* __restrict__ out_lo)
{
    __shared__ float k_s[64][68];
    __shared__ float v_s[64][64];

    const int qt = blockIdx.x;
    const int bh = blockIdx.y;
    const int b  = bh >> 4;
    const int h  = bh & 15;
    const int t  = threadIdx.x;
    const int g  = qt * 128 + t;

    const size_t seq_base = (size_t)b * S_ * (3 * D_);
    const size_t head_off = (size_t)h * DH_;
    const int numkt = 2 * qt + 2;
    const int orow = b * S_ + g;

#if HAS_TCGEN05
    uint64_t qp[32];
    {
        const ulonglong2* q128 = (const ulonglong2*)(qkv + seq_base + head_off +
                                                     (size_t)g * (3 * D_));
        #pragma unroll
        for (int i = 0; i < 16; i++) {
            const ulonglong2 u = q128[i];
            qp[2*i] = u.x; qp[2*i+1] = u.y;
        }
    }
    uint64_t op[32];
    #pragma unroll
    for (int i = 0; i < 32; i++) op[i] = 0ull;
    float m = -1e30f, l = 0.f;

    for (int kt = 0; kt < numkt; kt++) {
        const float* kp = qkv + seq_base + D_     + head_off + (size_t)(kt * 64) * (3 * D_);
        const float* vp = qkv + seq_base + 2 * D_ + head_off + (size_t)(kt * 64) * (3 * D_);
        #pragma unroll 4
        for (int i = t; i < 64 * 16; i += 128) {
            const int r = i >> 4;
            const int c = (i & 15) << 2;
            *(float4*)&k_s[r][c] = *(const float4*)(kp + (size_t)r * (3 * D_) + c);
            *(float4*)&v_s[r][c] = *(const float4*)(vp + (size_t)r * (3 * D_) + c);
        }
        __syncthreads();

        const bool edge = (kt >= 2 * qt);
        #pragma unroll
        for (int half = 0; half < 2; half++) {
            const int kbase = half * 32;
            float s[32];
            float mt = -1e30f;
            #pragma unroll 2
            for (int kc = 0; kc < 32; kc++) {
                const ulonglong2* krow = (const ulonglong2*)k_s[kbase + kc];
                uint64_t a0 = 0ull, a1 = 0ull, a2 = 0ull, a3 = 0ull;
                #pragma unroll
                for (int i = 0; i < 8; i++) {
                    const ulonglong2 u0 = krow[2*i];
                    const ulonglong2 u1 = krow[2*i+1];
                    ffma2(a0, qp[4*i],   u0.x);
                    ffma2(a1, qp[4*i+1], u0.y);
                    ffma2(a2, qp[4*i+2], u1.x);
                    ffma2(a3, qp[4*i+3], u1.y);
                }
                fadd2(a0, a2); fadd2(a1, a3); fadd2(a0, a1);
                float lo, hi; unpack2f(a0, lo, hi);
                float sc = (lo + hi) * 0.125f;
                if (edge && (kt * 64 + kbase + kc) > g) sc = -1e30f;
                s[kc] = sc;
                mt = fmaxf(mt, sc);
            }
            const float m_new = fmaxf(m, mt);
            const float corr  = __expf(m - m_new);
            l *= corr;
            const uint64_t corr2 = pack2f(corr, corr);
            #pragma unroll
            for (int i = 0; i < 32; i++) fmul2(op[i], corr2);
            #pragma unroll 2
            for (int kc = 0; kc < 32; kc++) {
                const float p = __expf(s[kc] - m_new);
                l += p;
                const uint64_t p2 = pack2f(p, p);
                const ulonglong2* vrow = (const ulonglong2*)v_s[kbase + kc];
                #pragma unroll
                for (int i = 0; i < 16; i++) {
                    const ulonglong2 u = vrow[i];
                    ffma2(op[2*i],   p2, u.x);
                    ffma2(op[2*i+1], p2, u.y);
                }
            }
            m = m_new;
        }
        __syncthreads();
    }

    const float inv_l = 1.0f / l;
    #pragma unroll
    for (int i = 0; i < 16; i++) {
        float4 v;
        unpack2f(op[2*i],   v.x, v.y);
        unpack2f(op[2*i+1], v.z, v.w);
        v.x *= inv_l; v.y *= inv_l; v.z *= inv_l; v.w *= inv_l;
        split_store4_tiled(out_hi, out_lo, orow, (int)head_off + i * 4, D_, v);
    }

#else
    float q[64];
    {
        const float* qpt = qkv + seq_base + head_off + (size_t)g * (3 * D_);
        #pragma unroll
        for (int d = 0; d < 64; d += 4) {
            const float4 u = *(const float4*)(qpt + d);
            q[d] = u.x; q[d+1] = u.y; q[d+2] = u.z; q[d+3] = u.w;
        }
    }
    float o[64];
    #pragma unroll
    for (int d = 0; d < 64; d++) o[d] = 0.f;
    float m = -1e30f, l = 0.f;

    for (int kt = 0; kt < numkt; kt++) {
        const float* kp = qkv + seq_base + D_     + head_off + (size_t)(kt * 64) * (3 * D_);
        const float* vp = qkv + seq_base + 2 * D_ + head_off + (size_t)(kt * 64) * (3 * D_);
        #pragma unroll 4
        for (int i = t; i < 64 * 16; i += 128) {
            const int r = i >> 4;
            const int c = (i & 15) << 2;
            *(float4*)&k_s[r][c] = *(const float4*)(kp + (size_t)r * (3 * D_) + c);
            *(float4*)&v_s[r][c] = *(const float4*)(vp + (size_t)r * (3 * D_) + c);
        }
        __syncthreads();

        const bool edge = (kt >= 2 * qt);
        #pragma unroll
        for (int half = 0; half < 2; half++) {
            const int kbase = half * 32;
            float s[32];
            float mt = -1e30f;
            #pragma unroll 2
            for (int kc = 0; kc < 32; kc++) {
                const float4* krow = (const float4*)k_s[kbase + kc];
                float d0 = 0.f, d1 = 0.f, d2 = 0.f, d3 = 0.f;
                #pragma unroll
                for (int d4 = 0; d4 < 16; d4++) {
                    const float4 kv = krow[d4];
                    d0 = fmaf(q[4*d4+0], kv.x, d0);
                    d1 = fmaf(q[4*d4+1], kv.y, d1);
                    d2 = fmaf(q[4*d4+2], kv.z, d2);
                    d3 = fmaf(q[4*d4+3], kv.w, d3);
                }
                float sc = (d0 + d1 + d2 + d3) * 0.125f;
                if (edge && (kt * 64 + kbase + kc) > g) sc = -1e30f;
                s[kc] = sc;
                mt = fmaxf(mt, sc);
            }
            const float m_new = fmaxf(m, mt);
            const float corr  = __expf(m - m_new);
            l *= corr;
            #pragma unroll
            for (int d = 0; d < 64; d++) o[d] *= corr;
            #pragma unroll 2
            for (int kc = 0; kc < 32; kc++) {
                const float p = __expf(s[kc] - m_new);
                l += p;
                const float4* vrow = (const float4*)v_s[kbase + kc];
                #pragma unroll
                for (int d4 = 0; d4 < 16; d4++) {
                    const float4 vv = vrow[d4];
                    o[4*d4+0] = fmaf(p, vv.x, o[4*d4+0]);
                    o[4*d4+1] = fmaf(p, vv.y, o[4*d4+1]);
                    o[4*d4+2] = fmaf(p, vv.z, o[4*d4+2]);
                    o[4*d4+3] = fmaf(p, vv.w, o[4*d4+3]);
                }
            }
            m = m_new;
        }
        __syncthreads();
    }

    const float inv_l = 1.0f / l;
    #pragma unroll
    for (int d4 = 0; d4 < 16; d4++) {
        float4 v;
        v.x = o[4*d4+0] * inv_l;
        v.y = o[4*d4+1] * inv_l;
        v.z = o[4*d4+2] * inv_l;
        v.w = o[4*d4+3] * inv_l;
        split_store4_tiled(out_hi, out_lo, orow, (int)head_off + d4 * 4, D_, v);
    }
#endif
}

// ---------------------------------------------------------------------------
// Launch
// ---------------------------------------------------------------------------
extern "C" void kernel_launch(void* const* d_in, const int* in_sizes, int n_in,
                              void* d_out, int out_size)
{
    const float* x     = (const float*)d_in[0];
    const float* ln1_g = (const float*)d_in[1];
    const float* ln1_b = (const float*)d_in[2];
    const float* w_qkv = (const float*)d_in[3];
    const float* b_qkv = (const float*)d_in[4];
    const float* w_o   = (const float*)d_in[5];
    const float* b_o   = (const float*)d_in[6];
    const float* ln2_g = (const float*)d_in[7];
    const float* ln2_b = (const float*)d_in[8];
    const float* w1    = (const float*)d_in[9];
    const float* b1    = (const float*)d_in[10];
    const float* w2    = (const float*)d_in[11];
    const float* b2    = (const float*)d_in[12];
    float* out = (float*)d_out;

    static bool inited = false;
    static float *p_qkv, *p_x2;
    static __nv_bfloat16 *p_act_h, *p_act_l, *p_big_h, *p_big_l;
    static __nv_bfloat16 *p_wqkv_h, *p_wqkv_l, *p_wo_h, *p_wo_l;
    static __nv_bfloat16 *p_w1_h, *p_w1_l, *p_w2_h, *p_w2_l;
    if (!inited) {
        void* p;
        cudaGetSymbolAddress(&p, g_qkv);    p_qkv    = (float*)p;
        cudaGetSymbolAddress(&p, g_x2);     p_x2     = (float*)p;
        cudaGetSymbolAddress(&p, g_act_hi); p_act_h  = (__nv_bfloat16*)p;
        cudaGetSymbolAddress(&p, g_act_lo); p_act_l  = (__nv_bfloat16*)p;
        cudaGetSymbolAddress(&p, g_big_hi); p_big_h  = (__nv_bfloat16*)p;
        cudaGetSymbolAddress(&p, g_big_lo); p_big_l  = (__nv_bfloat16*)p;
        cudaGetSymbolAddress(&p, g_wqkv_h); p_wqkv_h = (__nv_bfloat16*)p;
        cudaGetSymbolAddress(&p, g_wqkv_l); p_wqkv_l = (__nv_bfloat16*)p;
        cudaGetSymbolAddress(&p, g_wo_h);   p_wo_h   = (__nv_bfloat16*)p;
        cudaGetSymbolAddress(&p, g_wo_l);   p_wo_l   = (__nv_bfloat16*)p;
        cudaGetSymbolAddress(&p, g_w1_h);   p_w1_h   = (__nv_bfloat16*)p;
        cudaGetSymbolAddress(&p, g_w1_l);   p_w1_l   = (__nv_bfloat16*)p;
        cudaGetSymbolAddress(&p, g_w2_h);   p_w2_h   = (__nv_bfloat16*)p;
        cudaGetSymbolAddress(&p, g_w2_l);   p_w2_l   = (__nv_bfloat16*)p;
        cudaFuncSetAttribute(gemm_tc<EPI_BIAS>,       cudaFuncAttributeMaxDynamicSharedMemorySize, SMEM_GEMM);
        cudaFuncSetAttribute(gemm_tc<EPI_BIAS_RES>,   cudaFuncAttributeMaxDynamicSharedMemorySize, SMEM_GEMM);
        cudaFuncSetAttribute(gemm_tc<EPI_GELU_SPLIT>, cudaFuncAttributeMaxDynamicSharedMemorySize, SMEM_GEMM);
        inited = true;
    }

    // 0. weight splits -> tiled bf16 hi/lo
    split_kernel<<<(3*D_*D_/4 + 255)/256, 256>>>(w_qkv, p_wqkv_h, p_wqkv_l, 3*D_*D_/4, D_);
    split_kernel<<<(D_*D_/4   + 255)/256, 256>>>(w_o,   p_wo_h,   p_wo_l,   D_*D_/4,   D_);
    split_kernel<<<(FF_*D_/4  + 255)/256, 256>>>(w1,    p_w1_h,   p_w1_l,   FF_*D_/4,  D_);
    split_kernel<<<(D_*FF_/4  + 255)/256, 256>>>(w2,    p_w2_h,   p_w2_l,   D_*FF_/4,  FF_);

    // 1. LN1 + split (tiled)
    ln_split_kernel<<<TOK, 256>>>(x, ln1_g, ln1_b, p_act_h, p_act_l);

    // 2. QKV projection (persistent cg2, 74 clusters)
    gemm_tc<EPI_BIAS><<<GEMM_GRID, 320, SMEM_GEMM>>>(
        p_act_h, p_act_l, p_wqkv_h, p_wqkv_l, b_qkv, nullptr,
        p_qkv, nullptr, nullptr, 3*D_, D_);

    // 3. causal attention
    attn_kernel<<<dim3(S_/128, B_*H_), 128>>>(p_qkv, p_act_h, p_act_l);

    // 4. output projection + residual
    gemm_tc<EPI_BIAS_RES><<<GEMM_GRID, 320, SMEM_GEMM>>>(
        p_act_h, p_act_l, p_wo_h, p_wo_l, b_o, x,
        p_x2, nullptr, nullptr, D_, D_);

    // 5. LN2 + split (tiled)
    ln_split_kernel<<<TOK, 256>>>(p_x2, ln2_g, ln2_b, p_act_h, p_act_l);

    // 6. FFN up + GELU + split (tiled)
    gemm_tc<EPI_GELU_SPLIT><<<GEMM_GRID, 320, SMEM_GEMM>>>(
        p_act_h, p_act_l, p_w1_h, p_w1_l, b1, nullptr,
        nullptr, p_big_h, p_big_l, FF_, D_);

    // 7. FFN down + residual -> out
    gemm_tc<EPI_BIAS_RES><<<GEMM_GRID, 320, SMEM_GEMM>>>(
        p_big_h, p_big_l, p_w2_h, p_w2_l, b2, p_x2,
        out, nullptr, nullptr, D_, FF_);
}